// round 1
// baseline (speedup 1.0000x reference)
#include <cuda_runtime.h>
#include <math.h>

// Problem constants
#define TT   2048
#define DD   768
#define HH   12
#define DHH  64
#define LL   6
#define FFD  3072
#define VV   32000
#define QKV3 (3*DD)

// ---------------- scratch (static device globals; no dynamic alloc) ----------------
__device__ float g_h  [TT*DD];
__device__ float g_hn [TT*DD];
__device__ float g_qkv[TT*QKV3];
__device__ float g_ctx[TT*DD];
__device__ float g_ff [TT*FFD];
__device__ float g_nll[TT];
__device__ float g_val[TT];

// ---------------- reductions ----------------
__device__ __forceinline__ float warpSum(float v){
#pragma unroll
    for (int o = 16; o; o >>= 1) v += __shfl_xor_sync(0xffffffffu, v, o);
    return v;
}
__device__ __forceinline__ float warpMax(float v){
#pragma unroll
    for (int o = 16; o; o >>= 1) v = fmaxf(v, __shfl_xor_sync(0xffffffffu, v, o));
    return v;
}
__device__ float blockSum(float v){
    __shared__ float s[9];
    __syncthreads();                 // protect shared reuse across calls
    int lane = threadIdx.x & 31, w = threadIdx.x >> 5;
    v = warpSum(v);
    if (lane == 0) s[w] = v;
    __syncthreads();
    if (w == 0){
        float x = (lane < (int)(blockDim.x >> 5)) ? s[lane] : 0.f;
        x = warpSum(x);
        if (lane == 0) s[8] = x;
    }
    __syncthreads();
    return s[8];
}
__device__ float blockMax(float v){
    __shared__ float s[9];
    __syncthreads();
    int lane = threadIdx.x & 31, w = threadIdx.x >> 5;
    v = warpMax(v);
    if (lane == 0) s[w] = v;
    __syncthreads();
    if (w == 0){
        float x = (lane < (int)(blockDim.x >> 5)) ? s[lane] : -INFINITY;
        x = warpMax(x);
        if (lane == 0) s[8] = x;
    }
    __syncthreads();
    return s[8];
}

// ---------------- embedding ----------------
__global__ void embed_kernel(const int* __restrict__ x,
                             const float* __restrict__ tok,
                             const float* __restrict__ pos){
    int t  = blockIdx.x;
    int id = x[t];
    const float* tr = tok + (size_t)id * DD;
    const float* pr = pos + (size_t)t  * DD;
    for (int d = threadIdx.x; d < DD; d += blockDim.x)
        g_h[t*DD + d] = tr[d] + pr[d];
}

// ---------------- layernorm (one block per row) ----------------
__global__ void ln_kernel(const float* __restrict__ in, float* __restrict__ out,
                          const float* __restrict__ g, const float* __restrict__ b){
    __shared__ float row[DD];
    int t = blockIdx.x;
    const float* r = in + (size_t)t * DD;
    float s = 0.f;
    for (int d = threadIdx.x; d < DD; d += blockDim.x){ float v = r[d]; row[d] = v; s += v; }
    s = blockSum(s);
    float mean = s * (1.f / DD);
    float q = 0.f;
    for (int d = threadIdx.x; d < DD; d += blockDim.x){ float v = row[d] - mean; q += v*v; }
    q = blockSum(q);
    float rstd = rsqrtf(q * (1.f / DD) + 1e-5f);
    for (int d = threadIdx.x; d < DD; d += blockDim.x)
        out[t*DD + d] = (row[d] - mean) * rstd * g[d] + b[d];
}

// ---------------- SGEMM: C[M,N] = A[M,K] @ B[N,K]^T  (+bias)(+gelu)(+res) -----------
// 128x128 block tile, BK=16, 256 threads, 8x8 microtile.
template<int BIAS, int GELU, int RES>
__global__ __launch_bounds__(256)
void gemm_nt(const float* __restrict__ A, const float* __restrict__ B,
             const float* __restrict__ bias, const float* __restrict__ res,
             float* __restrict__ C, int M, int N, int K)
{
    __shared__ float As[16][132];
    __shared__ float Bs[16][132];
    const int tid = threadIdx.x;
    const int tx = tid & 15, ty = tid >> 4;
    const int m0 = blockIdx.y << 7, n0 = blockIdx.x << 7;
    const int lrow = tid >> 2;            // 0..63
    const int lcol = (tid & 3) << 2;      // 0,4,8,12
    const float* Ap = A + (size_t)(m0 + lrow) * K + lcol;
    const float* Bp = B + (size_t)(n0 + lrow) * K + lcol;

    float acc[8][8];
#pragma unroll
    for (int i = 0; i < 8; i++)
#pragma unroll
        for (int j = 0; j < 8; j++) acc[i][j] = 0.f;

    for (int k0 = 0; k0 < K; k0 += 16){
        float4 a0 = *(const float4*)(Ap + k0);
        float4 a1 = *(const float4*)(Ap + (size_t)64 * K + k0);
        float4 b0 = *(const float4*)(Bp + k0);
        float4 b1 = *(const float4*)(Bp + (size_t)64 * K + k0);
        __syncthreads();
        As[lcol+0][lrow]    = a0.x; As[lcol+1][lrow]    = a0.y; As[lcol+2][lrow]    = a0.z; As[lcol+3][lrow]    = a0.w;
        As[lcol+0][lrow+64] = a1.x; As[lcol+1][lrow+64] = a1.y; As[lcol+2][lrow+64] = a1.z; As[lcol+3][lrow+64] = a1.w;
        Bs[lcol+0][lrow]    = b0.x; Bs[lcol+1][lrow]    = b0.y; Bs[lcol+2][lrow]    = b0.z; Bs[lcol+3][lrow]    = b0.w;
        Bs[lcol+0][lrow+64] = b1.x; Bs[lcol+1][lrow+64] = b1.y; Bs[lcol+2][lrow+64] = b1.z; Bs[lcol+3][lrow+64] = b1.w;
        __syncthreads();
#pragma unroll
        for (int k = 0; k < 16; k++){
            float4 x0 = *(const float4*)&As[k][ty << 3];
            float4 x1 = *(const float4*)&As[k][(ty << 3) + 4];
            float4 y0 = *(const float4*)&Bs[k][tx << 3];
            float4 y1 = *(const float4*)&Bs[k][(tx << 3) + 4];
            float av[8] = {x0.x,x0.y,x0.z,x0.w,x1.x,x1.y,x1.z,x1.w};
            float bv[8] = {y0.x,y0.y,y0.z,y0.w,y1.x,y1.y,y1.z,y1.w};
#pragma unroll
            for (int i = 0; i < 8; i++)
#pragma unroll
                for (int j = 0; j < 8; j++)
                    acc[i][j] = fmaf(av[i], bv[j], acc[i][j]);
        }
    }

    float bb[8];
    if (BIAS){
        float4 c0 = *(const float4*)&bias[n0 + (tx << 3)];
        float4 c1 = *(const float4*)&bias[n0 + (tx << 3) + 4];
        bb[0]=c0.x; bb[1]=c0.y; bb[2]=c0.z; bb[3]=c0.w; bb[4]=c1.x; bb[5]=c1.y; bb[6]=c1.z; bb[7]=c1.w;
    }
#pragma unroll
    for (int i = 0; i < 8; i++){
        size_t m = (size_t)(m0 + (ty << 3) + i);
        size_t base = m * (size_t)N + n0 + (tx << 3);
        float v[8];
#pragma unroll
        for (int j = 0; j < 8; j++) v[j] = acc[i][j];
        if (BIAS){
#pragma unroll
            for (int j = 0; j < 8; j++) v[j] += bb[j];
        }
        if (GELU){
#pragma unroll
            for (int j = 0; j < 8; j++) v[j] = 0.5f * v[j] * (1.f + erff(v[j] * 0.70710678118654752f));
        }
        if (RES){
            float4 r0 = *(const float4*)&res[base];
            float4 r1 = *(const float4*)&res[base + 4];
            v[0]+=r0.x; v[1]+=r0.y; v[2]+=r0.z; v[3]+=r0.w; v[4]+=r1.x; v[5]+=r1.y; v[6]+=r1.z; v[7]+=r1.w;
        }
        *(float4*)&C[base]     = make_float4(v[0], v[1], v[2], v[3]);
        *(float4*)&C[base + 4] = make_float4(v[4], v[5], v[6], v[7]);
    }
}

// ---------------- flash attention: 64-query tile per block, streaming softmax -------
// grid: (T/64, H); 256 threads (16x16, 4x4 microtile). Reads g_qkv, writes g_ctx.
__global__ __launch_bounds__(256)
void attn_kernel(){
    extern __shared__ float sm[];
    float* Qs  = sm;                 // [64][68], Qs[d*68+q] (transposed, pre-scaled)
    float* Ks  = sm + 4352;          // [64][68], Ks[d*68+k]
    float* Vs  = sm + 2*4352;        // [64][68], Vs[k*68+d]
    float* Ss  = sm + 3*4352;        // [64][68], Ss[q*68+k]
    float* m_s = sm + 4*4352;
    float* l_s = m_s + 64;
    float* sc_s= l_s + 64;

    const int qb = blockIdx.x, hh = blockIdx.y;
    const int tid = threadIdx.x;
    const int tx = tid & 15, ty = tid >> 4;
    const int q0 = qb << 6;

    for (int idx = tid; idx < 4096; idx += 256){
        int r = idx >> 6, d = idx & 63;
        Qs[d*68 + r] = g_qkv[(q0 + r)*QKV3 + hh*DHH + d] * 0.125f;
    }
    if (tid < 64){ m_s[tid] = -INFINITY; l_s[tid] = 0.f; }

    float acc[4][4] = {{0.f,0.f,0.f,0.f},{0.f,0.f,0.f,0.f},{0.f,0.f,0.f,0.f},{0.f,0.f,0.f,0.f}};

    for (int j = 0; j <= qb; j++){
        __syncthreads();
        for (int idx = tid; idx < 4096; idx += 256){
            int r = idx >> 6, d = idx & 63;
            int t = (j << 6) + r;
            Ks[d*68 + r] = g_qkv[t*QKV3 + DD   + hh*DHH + d];
            Vs[r*68 + d] = g_qkv[t*QKV3 + 2*DD + hh*DHH + d];
        }
        __syncthreads();

        float s4[4][4] = {{0.f,0.f,0.f,0.f},{0.f,0.f,0.f,0.f},{0.f,0.f,0.f,0.f},{0.f,0.f,0.f,0.f}};
#pragma unroll 8
        for (int d = 0; d < 64; d++){
            float4 a = *(const float4*)&Qs[d*68 + (ty << 2)];
            float4 b = *(const float4*)&Ks[d*68 + (tx << 2)];
            float av[4] = {a.x,a.y,a.z,a.w};
            float bv[4] = {b.x,b.y,b.z,b.w};
#pragma unroll
            for (int i = 0; i < 4; i++)
#pragma unroll
                for (int jj = 0; jj < 4; jj++)
                    s4[i][jj] = fmaf(av[i], bv[jj], s4[i][jj]);
        }
        const bool diag = (j == qb);
#pragma unroll
        for (int i = 0; i < 4; i++){
            int q = (ty << 2) + i;
#pragma unroll
            for (int jj = 0; jj < 4; jj++){
                int k = (tx << 2) + jj;
                float v = s4[i][jj];
                if (diag && ((j << 6) + k) > (q0 + q)) v = -INFINITY;
                Ss[q*68 + k] = v;
            }
        }
        __syncthreads();

        if (tid < 64){
            int q = tid;
            float m_old = m_s[q];
            float mx = m_old;
#pragma unroll 8
            for (int k = 0; k < 64; k++) mx = fmaxf(mx, Ss[q*68 + k]);
            float sc = __expf(m_old - mx);
            float l = l_s[q] * sc;
#pragma unroll 4
            for (int k = 0; k < 64; k++){
                float p = __expf(Ss[q*68 + k] - mx);
                Ss[q*68 + k] = p;
                l += p;
            }
            m_s[q] = mx; l_s[q] = l; sc_s[q] = sc;
        }
        __syncthreads();

        float scr[4];
#pragma unroll
        for (int i = 0; i < 4; i++) scr[i] = sc_s[(ty << 2) + i];
#pragma unroll
        for (int i = 0; i < 4; i++)
#pragma unroll
            for (int jj = 0; jj < 4; jj++) acc[i][jj] *= scr[i];

#pragma unroll 8
        for (int k = 0; k < 64; k++){
            float4 b = *(const float4*)&Vs[k*68 + (tx << 2)];
            float bv[4] = {b.x,b.y,b.z,b.w};
#pragma unroll
            for (int i = 0; i < 4; i++){
                float p = Ss[((ty << 2) + i)*68 + k];
#pragma unroll
                for (int jj = 0; jj < 4; jj++)
                    acc[i][jj] = fmaf(p, bv[jj], acc[i][jj]);
            }
        }
    }

    float inv[4];
#pragma unroll
    for (int i = 0; i < 4; i++) inv[i] = 1.f / l_s[(ty << 2) + i];
#pragma unroll
    for (int i = 0; i < 4; i++){
        int q = q0 + (ty << 2) + i;
#pragma unroll
        for (int jj = 0; jj < 4; jj++)
            g_ctx[q*DD + hh*DHH + (tx << 2) + jj] = acc[i][jj] * inv[i];
    }
}

// ---------------- loss: per-row logsumexp + nll, then reduce ----------------
__global__ void row_lse_kernel(const float* __restrict__ logits, const int* __restrict__ tgt){
    int t = blockIdx.x;
    const float* row = logits + (size_t)t * VV;
    float mx = -INFINITY;
    for (int i = threadIdx.x; i < VV; i += blockDim.x) mx = fmaxf(mx, row[i]);
    mx = blockMax(mx);
    float s = 0.f;
    for (int i = threadIdx.x; i < VV; i += blockDim.x) s += expf(row[i] - mx);
    s = blockSum(s);
    if (threadIdx.x == 0){
        int tg = tgt[t];
        float lse = mx + logf(s);
        float nll = lse - row[tg];
        g_nll[t] = (tg != 0) ? nll : 0.f;
        g_val[t] = (tg != 0) ? 1.f : 0.f;
    }
}

__global__ void loss_reduce_kernel(float* __restrict__ out_loss){
    float a = 0.f, b = 0.f;
    for (int t = threadIdx.x; t < TT; t += blockDim.x){ a += g_nll[t]; b += g_val[t]; }
    a = blockSum(a);
    b = blockSum(b);
    if (threadIdx.x == 0) *out_loss = a / fmaxf(b, 1.f);
}

// ---------------- launch ----------------
extern "C" void kernel_launch(void* const* d_in, const int* in_sizes, int n_in,
                              void* d_out, int out_size){
    (void)in_sizes; (void)n_in;
    const int*   x     = (const int*)  d_in[0];
    const int*   tgt   = (const int*)  d_in[1];
    const float* tok   = (const float*)d_in[2];
    const float* pos   = (const float*)d_in[3];
    const float* Wqkv  = (const float*)d_in[4];
    const float* Wo    = (const float*)d_in[5];
    const float* ln1g  = (const float*)d_in[6];
    const float* ln1b  = (const float*)d_in[7];
    const float* ln2g  = (const float*)d_in[8];
    const float* ln2b  = (const float*)d_in[9];
    const float* W1    = (const float*)d_in[10];
    const float* b1    = (const float*)d_in[11];
    const float* W2    = (const float*)d_in[12];
    const float* b2    = (const float*)d_in[13];
    const float* lnfg  = (const float*)d_in[14];
    const float* lnfb  = (const float*)d_in[15];
    float* out = (float*)d_out;

    float *ph, *phn, *pqkv, *pctx, *pff;
    cudaGetSymbolAddress((void**)&ph,   g_h);
    cudaGetSymbolAddress((void**)&phn,  g_hn);
    cudaGetSymbolAddress((void**)&pqkv, g_qkv);
    cudaGetSymbolAddress((void**)&pctx, g_ctx);
    cudaGetSymbolAddress((void**)&pff,  g_ff);

    const size_t attn_smem = (4u*64u*68u + 3u*64u) * sizeof(float); // ~70.4 KB
    cudaFuncSetAttribute(attn_kernel, cudaFuncAttributeMaxDynamicSharedMemorySize, (int)attn_smem);

    embed_kernel<<<TT, 256>>>(x, tok, pos);

    for (int l = 0; l < LL; l++){
        ln_kernel<<<TT, 256>>>(ph, phn, ln1g + l*DD, ln1b + l*DD);
        gemm_nt<0,0,0><<<dim3(QKV3/128, TT/128), 256>>>(phn, Wqkv + (size_t)l*QKV3*DD,
                                                        nullptr, nullptr, pqkv, TT, QKV3, DD);
        attn_kernel<<<dim3(TT/64, HH), 256, attn_smem>>>();
        gemm_nt<0,0,1><<<dim3(DD/128, TT/128), 256>>>(pctx, Wo + (size_t)l*DD*DD,
                                                      nullptr, ph, ph, TT, DD, DD);
        ln_kernel<<<TT, 256>>>(ph, phn, ln2g + l*DD, ln2b + l*DD);
        gemm_nt<1,1,0><<<dim3(FFD/128, TT/128), 256>>>(phn, W1 + (size_t)l*FFD*DD,
                                                       b1 + (size_t)l*FFD, nullptr, pff, TT, FFD, DD);
        gemm_nt<1,0,1><<<dim3(DD/128, TT/128), 256>>>(pff, W2 + (size_t)l*DD*FFD,
                                                      b2 + (size_t)l*DD, ph, ph, TT, DD, FFD);
    }

    ln_kernel<<<TT, 256>>>(ph, phn, lnfg, lnfb);
    gemm_nt<0,0,0><<<dim3(VV/128, TT/128), 256>>>(phn, tok, nullptr, nullptr, out, TT, VV, DD);

    row_lse_kernel<<<TT, 256>>>(out, tgt);
    if (out_size > TT * VV)
        loss_reduce_kernel<<<1, 256>>>(out + (size_t)TT * VV);
}

// round 3
// speedup vs baseline: 1.7679x; 1.7679x over previous
#include <cuda_runtime.h>
#include <cuda_bf16.h>
#include <math.h>
#include <stdint.h>

// Problem constants
#define TT   2048
#define DD   768
#define HH   12
#define DHH  64
#define LL   6
#define FFD  3072
#define VV   32000
#define QKV3 (3*DD)

// ---------------- scratch (static device globals; no dynamic alloc) ----------------
__device__ float g_h  [TT*DD];
__device__ float g_hn [TT*DD];
__device__ float g_qkv[TT*QKV3];
__device__ float g_ctx[TT*DD];
__device__ float g_ff [TT*FFD];
__device__ float g_nll[TT];
__device__ float g_val[TT];

// ---------------- helpers ----------------
__device__ __forceinline__ uint32_t smem_u32(const void* p){
    uint32_t a;
    asm("{ .reg .u64 t; cvta.to.shared.u64 t, %1; cvt.u32.u64 %0, t; }" : "=r"(a) : "l"(p));
    return a;
}
// pack 2 floats -> bf16x2 (x0 -> low half)
__device__ __forceinline__ uint32_t packbf(float x0, float x1){
    uint32_t r;
    asm("cvt.rn.bf16x2.f32 %0, %1, %2;" : "=r"(r) : "f"(x1), "f"(x0));
    return r;
}
__device__ __forceinline__ void ldsm4(uint32_t &r0, uint32_t &r1, uint32_t &r2, uint32_t &r3,
                                      uint32_t addr){
    asm volatile("ldmatrix.sync.aligned.m8n8.x4.shared.b16 {%0,%1,%2,%3}, [%4];"
        : "=r"(r0), "=r"(r1), "=r"(r2), "=r"(r3) : "r"(addr));
}
__device__ __forceinline__ void mma16816(float* d, const uint32_t* a, const uint32_t* b){
    asm volatile("mma.sync.aligned.m16n8k16.row.col.f32.bf16.bf16.f32 "
        "{%0,%1,%2,%3}, {%4,%5,%6,%7}, {%8,%9}, {%0,%1,%2,%3};"
        : "+f"(d[0]), "+f"(d[1]), "+f"(d[2]), "+f"(d[3])
        : "r"(a[0]), "r"(a[1]), "r"(a[2]), "r"(a[3]), "r"(b[0]), "r"(b[1]));
}

// ---------------- reductions ----------------
__device__ __forceinline__ float warpSum(float v){
#pragma unroll
    for (int o = 16; o; o >>= 1) v += __shfl_xor_sync(0xffffffffu, v, o);
    return v;
}
__device__ __forceinline__ float warpMax(float v){
#pragma unroll
    for (int o = 16; o; o >>= 1) v = fmaxf(v, __shfl_xor_sync(0xffffffffu, v, o));
    return v;
}
__device__ float blockSum(float v){
    __shared__ float s[9];
    __syncthreads();
    int lane = threadIdx.x & 31, w = threadIdx.x >> 5;
    v = warpSum(v);
    if (lane == 0) s[w] = v;
    __syncthreads();
    if (w == 0){
        float x = (lane < (int)(blockDim.x >> 5)) ? s[lane] : 0.f;
        x = warpSum(x);
        if (lane == 0) s[8] = x;
    }
    __syncthreads();
    return s[8];
}
__device__ float blockMax(float v){
    __shared__ float s[9];
    __syncthreads();
    int lane = threadIdx.x & 31, w = threadIdx.x >> 5;
    v = warpMax(v);
    if (lane == 0) s[w] = v;
    __syncthreads();
    if (w == 0){
        float x = (lane < (int)(blockDim.x >> 5)) ? s[lane] : -INFINITY;
        x = warpMax(x);
        if (lane == 0) s[8] = x;
    }
    __syncthreads();
    return s[8];
}

// ---------------- embedding ----------------
__global__ void embed_kernel(const int* __restrict__ x,
                             const float* __restrict__ tok,
                             const float* __restrict__ pos){
    int t  = blockIdx.x;
    int id = x[t];
    const float* tr = tok + (size_t)id * DD;
    const float* pr = pos + (size_t)t  * DD;
    for (int d = threadIdx.x; d < DD; d += blockDim.x)
        g_h[t*DD + d] = tr[d] + pr[d];
}

// ---------------- layernorm ----------------
__global__ void ln_kernel(const float* __restrict__ in, float* __restrict__ out,
                          const float* __restrict__ g, const float* __restrict__ b){
    __shared__ float row[DD];
    int t = blockIdx.x;
    const float* r = in + (size_t)t * DD;
    float s = 0.f;
    for (int d = threadIdx.x; d < DD; d += blockDim.x){ float v = r[d]; row[d] = v; s += v; }
    s = blockSum(s);
    float mean = s * (1.f / DD);
    float q = 0.f;
    for (int d = threadIdx.x; d < DD; d += blockDim.x){ float v = row[d] - mean; q += v*v; }
    q = blockSum(q);
    float rstd = rsqrtf(q * (1.f / DD) + 1e-5f);
    for (int d = threadIdx.x; d < DD; d += blockDim.x)
        out[t*DD + d] = (row[d] - mean) * rstd * g[d] + b[d];
}

// ================== bf16-split tensor-core GEMM (mma.sync, sm_80-class path) =========
// C[M,N] = A[M,K] @ B[N,K]^T (+bias)(+gelu)(+res), fp32 in/out.
// 128x128 CTA tile, BK=32, 8 warps (2x4), warp tile 64x32.
// 3-product bf16 hi/lo split: A*B ~= Ahi*Bhi + Ahi*Blo + Alo*Bhi (residual ~2^-16).
// smem/stage: Ahi[128x80B] Alo Bhi Blo = 40960B; double buffered = 81920B.
#define ROWB 80
#define STAGE_B 40960
#define G_SMEM (2*STAGE_B)

template<int BIASF, int GELUF, int RESF>
__global__ __launch_bounds__(256, 1)
void gemm_mma(const float* __restrict__ A, const float* __restrict__ B,
              const float* __restrict__ bias, const float* __restrict__ res,
              float* __restrict__ C, int M, int N, int K)
{
    extern __shared__ char smem[];
    const uint32_t sb = smem_u32(smem);
    const int tid = threadIdx.x, wid = tid >> 5, lane = tid & 31;
    const int m0 = blockIdx.x << 7, n0 = blockIdx.y << 7;
    const int wm = (wid >> 2) << 6;     // 0 or 64
    const int wn = (wid & 3) << 5;      // 0,32,64,96

    // loader mapping: 2 threads per row, 4 float4 slots each
    const int lrow = tid >> 1;          // 0..127
    const int j0   = (tid & 1) << 2;    // 0 or 4 (float4 slot)
    const float* Ap = A + (size_t)(m0 + lrow) * K + (j0 << 2);
    const float* Bp = B + (size_t)(n0 + lrow) * K + (j0 << 2);
    const uint32_t stsA = sb + lrow * ROWB + (j0 << 3);
    const uint32_t stsB = stsA + 2 * 10240;

    float acc[4][4][4];
#pragma unroll
    for (int i = 0; i < 4; i++)
#pragma unroll
        for (int j = 0; j < 4; j++)
#pragma unroll
            for (int k = 0; k < 4; k++) acc[i][j][k] = 0.f;

    const int NC = K >> 5;
    float4 aR[4], bR[4];

    // prologue: chunk 0 -> stage 0
#pragma unroll
    for (int j = 0; j < 4; j++){
        aR[j] = *(const float4*)(Ap + (j << 2));
        bR[j] = *(const float4*)(Bp + (j << 2));
    }
#pragma unroll
    for (int j = 0; j < 4; j++){
        uint32_t h0 = packbf(aR[j].x, aR[j].y), h1 = packbf(aR[j].z, aR[j].w);
        float l0 = aR[j].x - __uint_as_float(h0 << 16);
        float l1 = aR[j].y - __uint_as_float(h0 & 0xffff0000u);
        float l2 = aR[j].z - __uint_as_float(h1 << 16);
        float l3 = aR[j].w - __uint_as_float(h1 & 0xffff0000u);
        *(uint2*)(uintptr_t)0; // placeholder removed below
        asm volatile("st.shared.v2.b32 [%0], {%1,%2};" :: "r"(stsA + (j << 3)), "r"(h0), "r"(h1) : "memory");
        asm volatile("st.shared.v2.b32 [%0], {%1,%2};" :: "r"(stsA + 10240 + (j << 3)),
                     "r"(packbf(l0, l1)), "r"(packbf(l2, l3)) : "memory");
        uint32_t g0 = packbf(bR[j].x, bR[j].y), g1 = packbf(bR[j].z, bR[j].w);
        float m0f = bR[j].x - __uint_as_float(g0 << 16);
        float m1f = bR[j].y - __uint_as_float(g0 & 0xffff0000u);
        float m2f = bR[j].z - __uint_as_float(g1 << 16);
        float m3f = bR[j].w - __uint_as_float(g1 & 0xffff0000u);
        asm volatile("st.shared.v2.b32 [%0], {%1,%2};" :: "r"(stsB + (j << 3)), "r"(g0), "r"(g1) : "memory");
        asm volatile("st.shared.v2.b32 [%0], {%1,%2};" :: "r"(stsB + 10240 + (j << 3)),
                     "r"(packbf(m0f, m1f)), "r"(packbf(m2f, m3f)) : "memory");
    }
    __syncthreads();

    // ldmatrix lane addressing pieces
    const int g  = lane >> 3, lr = lane & 7;
    const int arow_off = ((g & 1) << 3) + lr;   // A: (g&1)*8 + lane%8
    const int akb      = (g >> 1) << 4;         // A: (g/2)*16 bytes
    const int brow_off = ((g >> 1) << 3) + lr;  // B: (g/2)*8 + lane%8
    const int bkb      = (g & 1) << 4;          // B: (g%2)*16 bytes

    for (int c = 0; c < NC; c++){
        const uint32_t st = sb + (c & 1) * STAGE_B;

        // prefetch next chunk
        if (c + 1 < NC){
#pragma unroll
            for (int j = 0; j < 4; j++){
                aR[j] = *(const float4*)(Ap + (size_t)(c + 1) * 32 + (j << 2));
                bR[j] = *(const float4*)(Bp + (size_t)(c + 1) * 32 + (j << 2));
            }
        }

        // compute on current stage
#pragma unroll
        for (int h = 0; h < 2; h++){
            uint32_t Ah[4][4], Al[4][4], Bh[4][2], Bl[4][2];
#pragma unroll
            for (int mt = 0; mt < 4; mt++){
                uint32_t ad = st + (uint32_t)((wm + (mt << 4) + arow_off) * ROWB + (h << 5) + akb);
                ldsm4(Ah[mt][0], Ah[mt][1], Ah[mt][2], Ah[mt][3], ad);
                ldsm4(Al[mt][0], Al[mt][1], Al[mt][2], Al[mt][3], ad + 10240);
            }
#pragma unroll
            for (int nt2 = 0; nt2 < 2; nt2++){
                uint32_t bd = st + 20480 + (uint32_t)((wn + (nt2 << 4) + brow_off) * ROWB + (h << 5) + bkb);
                uint32_t r0, r1, r2, r3;
                ldsm4(r0, r1, r2, r3, bd);
                Bh[2*nt2][0] = r0; Bh[2*nt2][1] = r1; Bh[2*nt2+1][0] = r2; Bh[2*nt2+1][1] = r3;
                ldsm4(r0, r1, r2, r3, bd + 10240);
                Bl[2*nt2][0] = r0; Bl[2*nt2][1] = r1; Bl[2*nt2+1][0] = r2; Bl[2*nt2+1][1] = r3;
            }
#pragma unroll
            for (int mt = 0; mt < 4; mt++)
#pragma unroll
                for (int nt = 0; nt < 4; nt++){
                    mma16816(acc[mt][nt], Ah[mt], Bh[nt]);
                    mma16816(acc[mt][nt], Ah[mt], Bl[nt]);
                    mma16816(acc[mt][nt], Al[mt], Bh[nt]);
                }
        }

        // store next chunk into other stage
        if (c + 1 < NC){
            const uint32_t dsA = stsA + ((c + 1) & 1) * STAGE_B;
            const uint32_t dsB = stsB + ((c + 1) & 1) * STAGE_B;
#pragma unroll
            for (int j = 0; j < 4; j++){
                uint32_t h0 = packbf(aR[j].x, aR[j].y), h1 = packbf(aR[j].z, aR[j].w);
                float l0 = aR[j].x - __uint_as_float(h0 << 16);
                float l1 = aR[j].y - __uint_as_float(h0 & 0xffff0000u);
                float l2 = aR[j].z - __uint_as_float(h1 << 16);
                float l3 = aR[j].w - __uint_as_float(h1 & 0xffff0000u);
                asm volatile("st.shared.v2.b32 [%0], {%1,%2};" :: "r"(dsA + (j << 3)), "r"(h0), "r"(h1) : "memory");
                asm volatile("st.shared.v2.b32 [%0], {%1,%2};" :: "r"(dsA + 10240 + (j << 3)),
                             "r"(packbf(l0, l1)), "r"(packbf(l2, l3)) : "memory");
                uint32_t g0 = packbf(bR[j].x, bR[j].y), g1 = packbf(bR[j].z, bR[j].w);
                float q0 = bR[j].x - __uint_as_float(g0 << 16);
                float q1 = bR[j].y - __uint_as_float(g0 & 0xffff0000u);
                float q2 = bR[j].z - __uint_as_float(g1 << 16);
                float q3 = bR[j].w - __uint_as_float(g1 & 0xffff0000u);
                asm volatile("st.shared.v2.b32 [%0], {%1,%2};" :: "r"(dsB + (j << 3)), "r"(g0), "r"(g1) : "memory");
                asm volatile("st.shared.v2.b32 [%0], {%1,%2};" :: "r"(dsB + 10240 + (j << 3)),
                             "r"(packbf(q0, q1)), "r"(packbf(q2, q3)) : "memory");
            }
        }
        __syncthreads();
    }

    // epilogue
    const int qr = lane >> 2, qc = lane & 3;
#pragma unroll
    for (int mt = 0; mt < 4; mt++){
#pragma unroll
        for (int p = 0; p < 2; p++){
            int m = m0 + wm + (mt << 4) + qr + (p << 3);
            size_t rowbase = (size_t)m * N;
#pragma unroll
            for (int nt = 0; nt < 4; nt++){
                int n = n0 + wn + (nt << 3) + (qc << 1);
                float v0 = acc[mt][nt][2*p], v1 = acc[mt][nt][2*p + 1];
                if (BIASF){ v0 += bias[n]; v1 += bias[n + 1]; }
                if (GELUF){
                    v0 = 0.5f * v0 * (1.f + erff(v0 * 0.70710678118654752f));
                    v1 = 0.5f * v1 * (1.f + erff(v1 * 0.70710678118654752f));
                }
                if (RESF){
                    float2 rr = *(const float2*)&res[rowbase + n];
                    v0 += rr.x; v1 += rr.y;
                }
                *(float2*)&C[rowbase + n] = make_float2(v0, v1);
            }
        }
    }
}

// ---------------- flash attention (fp32 SIMT) ----------------
__global__ __launch_bounds__(256)
void attn_kernel(){
    extern __shared__ float sm[];
    float* Qs  = sm;
    float* Ks  = sm + 4352;
    float* Vs  = sm + 2*4352;
    float* Ss  = sm + 3*4352;
    float* m_s = sm + 4*4352;
    float* l_s = m_s + 64;
    float* sc_s= l_s + 64;

    const int qb = blockIdx.x, hh = blockIdx.y;
    const int tid = threadIdx.x;
    const int tx = tid & 15, ty = tid >> 4;
    const int q0 = qb << 6;

    for (int idx = tid; idx < 4096; idx += 256){
        int r = idx >> 6, d = idx & 63;
        Qs[d*68 + r] = g_qkv[(q0 + r)*QKV3 + hh*DHH + d] * 0.125f;
    }
    if (tid < 64){ m_s[tid] = -INFINITY; l_s[tid] = 0.f; }

    float acc[4][4] = {{0.f,0.f,0.f,0.f},{0.f,0.f,0.f,0.f},{0.f,0.f,0.f,0.f},{0.f,0.f,0.f,0.f}};

    for (int j = 0; j <= qb; j++){
        __syncthreads();
        for (int idx = tid; idx < 4096; idx += 256){
            int r = idx >> 6, d = idx & 63;
            int t = (j << 6) + r;
            Ks[d*68 + r] = g_qkv[t*QKV3 + DD   + hh*DHH + d];
            Vs[r*68 + d] = g_qkv[t*QKV3 + 2*DD + hh*DHH + d];
        }
        __syncthreads();

        float s4[4][4] = {{0.f,0.f,0.f,0.f},{0.f,0.f,0.f,0.f},{0.f,0.f,0.f,0.f},{0.f,0.f,0.f,0.f}};
#pragma unroll 8
        for (int d = 0; d < 64; d++){
            float4 a = *(const float4*)&Qs[d*68 + (ty << 2)];
            float4 b = *(const float4*)&Ks[d*68 + (tx << 2)];
            float av[4] = {a.x,a.y,a.z,a.w};
            float bv[4] = {b.x,b.y,b.z,b.w};
#pragma unroll
            for (int i = 0; i < 4; i++)
#pragma unroll
                for (int jj = 0; jj < 4; jj++)
                    s4[i][jj] = fmaf(av[i], bv[jj], s4[i][jj]);
        }
        const bool diag = (j == qb);
#pragma unroll
        for (int i = 0; i < 4; i++){
            int q = (ty << 2) + i;
#pragma unroll
            for (int jj = 0; jj < 4; jj++){
                int k = (tx << 2) + jj;
                float v = s4[i][jj];
                if (diag && ((j << 6) + k) > (q0 + q)) v = -INFINITY;
                Ss[q*68 + k] = v;
            }
        }
        __syncthreads();

        if (tid < 64){
            int q = tid;
            float m_old = m_s[q];
            float mx = m_old;
#pragma unroll 8
            for (int k = 0; k < 64; k++) mx = fmaxf(mx, Ss[q*68 + k]);
            float sc = __expf(m_old - mx);
            float l = l_s[q] * sc;
#pragma unroll 4
            for (int k = 0; k < 64; k++){
                float p = __expf(Ss[q*68 + k] - mx);
                Ss[q*68 + k] = p;
                l += p;
            }
            m_s[q] = mx; l_s[q] = l; sc_s[q] = sc;
        }
        __syncthreads();

        float scr[4];
#pragma unroll
        for (int i = 0; i < 4; i++) scr[i] = sc_s[(ty << 2) + i];
#pragma unroll
        for (int i = 0; i < 4; i++)
#pragma unroll
            for (int jj = 0; jj < 4; jj++) acc[i][jj] *= scr[i];

#pragma unroll 8
        for (int k = 0; k < 64; k++){
            float4 b = *(const float4*)&Vs[k*68 + (tx << 2)];
            float bv[4] = {b.x,b.y,b.z,b.w};
#pragma unroll
            for (int i = 0; i < 4; i++){
                float p = Ss[((ty << 2) + i)*68 + k];
#pragma unroll
                for (int jj = 0; jj < 4; jj++)
                    acc[i][jj] = fmaf(p, bv[jj], acc[i][jj]);
            }
        }
    }

    float inv[4];
#pragma unroll
    for (int i = 0; i < 4; i++) inv[i] = 1.f / l_s[(ty << 2) + i];
#pragma unroll
    for (int i = 0; i < 4; i++){
        int q = q0 + (ty << 2) + i;
#pragma unroll
        for (int jj = 0; jj < 4; jj++)
            g_ctx[q*DD + hh*DHH + (tx << 2) + jj] = acc[i][jj] * inv[i];
    }
}

// ---------------- loss ----------------
__global__ void row_lse_kernel(const float* __restrict__ logits, const int* __restrict__ tgt){
    int t = blockIdx.x;
    const float* row = logits + (size_t)t * VV;
    float mx = -INFINITY;
    for (int i = threadIdx.x; i < VV; i += blockDim.x) mx = fmaxf(mx, row[i]);
    mx = blockMax(mx);
    float s = 0.f;
    for (int i = threadIdx.x; i < VV; i += blockDim.x) s += expf(row[i] - mx);
    s = blockSum(s);
    if (threadIdx.x == 0){
        int tg = tgt[t];
        float lse = mx + logf(s);
        float nll = lse - row[tg];
        g_nll[t] = (tg != 0) ? nll : 0.f;
        g_val[t] = (tg != 0) ? 1.f : 0.f;
    }
}

__global__ void loss_reduce_kernel(float* __restrict__ out_loss){
    float a = 0.f, b = 0.f;
    for (int t = threadIdx.x; t < TT; t += blockDim.x){ a += g_nll[t]; b += g_val[t]; }
    a = blockSum(a);
    b = blockSum(b);
    if (threadIdx.x == 0) *out_loss = a / fmaxf(b, 1.f);
}

// ---------------- launch ----------------
extern "C" void kernel_launch(void* const* d_in, const int* in_sizes, int n_in,
                              void* d_out, int out_size){
    (void)in_sizes; (void)n_in;
    const int*   x     = (const int*)  d_in[0];
    const int*   tgt   = (const int*)  d_in[1];
    const float* tok   = (const float*)d_in[2];
    const float* pos   = (const float*)d_in[3];
    const float* Wqkv  = (const float*)d_in[4];
    const float* Wo    = (const float*)d_in[5];
    const float* ln1g  = (const float*)d_in[6];
    const float* ln1b  = (const float*)d_in[7];
    const float* ln2g  = (const float*)d_in[8];
    const float* ln2b  = (const float*)d_in[9];
    const float* W1    = (const float*)d_in[10];
    const float* b1    = (const float*)d_in[11];
    const float* W2    = (const float*)d_in[12];
    const float* b2    = (const float*)d_in[13];
    const float* lnfg  = (const float*)d_in[14];
    const float* lnfb  = (const float*)d_in[15];
    float* out = (float*)d_out;

    float *ph, *phn, *pqkv, *pctx, *pff;
    cudaGetSymbolAddress((void**)&ph,   g_h);
    cudaGetSymbolAddress((void**)&phn,  g_hn);
    cudaGetSymbolAddress((void**)&pqkv, g_qkv);
    cudaGetSymbolAddress((void**)&pctx, g_ctx);
    cudaGetSymbolAddress((void**)&pff,  g_ff);

    cudaFuncSetAttribute(gemm_mma<0,0,0>, cudaFuncAttributeMaxDynamicSharedMemorySize, G_SMEM);
    cudaFuncSetAttribute(gemm_mma<0,0,1>, cudaFuncAttributeMaxDynamicSharedMemorySize, G_SMEM);
    cudaFuncSetAttribute(gemm_mma<1,1,0>, cudaFuncAttributeMaxDynamicSharedMemorySize, G_SMEM);
    cudaFuncSetAttribute(gemm_mma<1,0,1>, cudaFuncAttributeMaxDynamicSharedMemorySize, G_SMEM);

    const size_t attn_smem = (4u*64u*68u + 3u*64u) * sizeof(float);
    cudaFuncSetAttribute(attn_kernel, cudaFuncAttributeMaxDynamicSharedMemorySize, (int)attn_smem);

    embed_kernel<<<TT, 256>>>(x, tok, pos);

    for (int l = 0; l < LL; l++){
        ln_kernel<<<TT, 256>>>(ph, phn, ln1g + l*DD, ln1b + l*DD);
        gemm_mma<0,0,0><<<dim3(TT/128, QKV3/128), 256, G_SMEM>>>(
            phn, Wqkv + (size_t)l*QKV3*DD, nullptr, nullptr, pqkv, TT, QKV3, DD);
        attn_kernel<<<dim3(TT/64, HH), 256, attn_smem>>>();
        gemm_mma<0,0,1><<<dim3(TT/128, DD/128), 256, G_SMEM>>>(
            pctx, Wo + (size_t)l*DD*DD, nullptr, ph, ph, TT, DD, DD);
        ln_kernel<<<TT, 256>>>(ph, phn, ln2g + l*DD, ln2b + l*DD);
        gemm_mma<1,1,0><<<dim3(TT/128, FFD/128), 256, G_SMEM>>>(
            phn, W1 + (size_t)l*FFD*DD, b1 + (size_t)l*FFD, nullptr, pff, TT, FFD, DD);
        gemm_mma<1,0,1><<<dim3(TT/128, DD/128), 256, G_SMEM>>>(
            pff, W2 + (size_t)l*DD*FFD, b2 + (size_t)l*DD, ph, ph, TT, DD, FFD);
    }

    ln_kernel<<<TT, 256>>>(ph, phn, lnfg, lnfb);
    gemm_mma<0,0,0><<<dim3(TT/128, VV/128), 256, G_SMEM>>>(
        phn, tok, nullptr, nullptr, out, TT, VV, DD);

    row_lse_kernel<<<TT, 256>>>(out, tgt);
    if (out_size > TT * VV)
        loss_reduce_kernel<<<1, 256>>>(out + (size_t)TT * VV);
}

// round 6
// speedup vs baseline: 2.4591x; 1.3910x over previous
#include <cuda_runtime.h>
#include <cuda_bf16.h>
#include <math.h>
#include <stdint.h>

// Problem constants
#define TT   2048
#define DD   768
#define HH   12
#define DHH  64
#define LL   6
#define FFD  3072
#define VV   32000
#define QKV3 (3*DD)

// ---------------- scratch ----------------
__device__ float g_h  [TT*DD];
__device__ float g_hn [TT*DD];
__device__ float g_qkv[TT*QKV3];
__device__ float g_ctx[TT*DD];
__device__ float g_ff [TT*FFD];
__device__ float g_nll[TT];
__device__ float g_val[TT];

// ---------------- helpers ----------------
__device__ __forceinline__ uint32_t smem_u32(const void* p){
    uint32_t a;
    asm("{ .reg .u64 t; cvta.to.shared.u64 t, %1; cvt.u32.u64 %0, t; }" : "=r"(a) : "l"(p));
    return a;
}
__device__ __forceinline__ uint32_t packbf(float x0, float x1){
    uint32_t r;
    asm("cvt.rn.bf16x2.f32 %0, %1, %2;" : "=r"(r) : "f"(x1), "f"(x0));
    return r;
}
__device__ __forceinline__ float ex2f(float x){
    float y; asm("ex2.approx.f32 %0, %1;" : "=f"(y) : "f"(x)); return y;
}
__device__ __forceinline__ void ldsm4(uint32_t &r0, uint32_t &r1, uint32_t &r2, uint32_t &r3,
                                      uint32_t addr){
    asm volatile("ldmatrix.sync.aligned.m8n8.x4.shared.b16 {%0,%1,%2,%3}, [%4];"
        : "=r"(r0), "=r"(r1), "=r"(r2), "=r"(r3) : "r"(addr));
}
__device__ __forceinline__ void ldsm4t(uint32_t &r0, uint32_t &r1, uint32_t &r2, uint32_t &r3,
                                       uint32_t addr){
    asm volatile("ldmatrix.sync.aligned.m8n8.x4.trans.shared.b16 {%0,%1,%2,%3}, [%4];"
        : "=r"(r0), "=r"(r1), "=r"(r2), "=r"(r3) : "r"(addr));
}
__device__ __forceinline__ void mma16816(float* d, const uint32_t* a, const uint32_t* b){
    asm volatile("mma.sync.aligned.m16n8k16.row.col.f32.bf16.bf16.f32 "
        "{%0,%1,%2,%3}, {%4,%5,%6,%7}, {%8,%9}, {%0,%1,%2,%3};"
        : "+f"(d[0]), "+f"(d[1]), "+f"(d[2]), "+f"(d[3])
        : "r"(a[0]), "r"(a[1]), "r"(a[2]), "r"(a[3]), "r"(b[0]), "r"(b[1]));
}

// ---------------- reductions ----------------
__device__ __forceinline__ float warpSum(float v){
#pragma unroll
    for (int o = 16; o; o >>= 1) v += __shfl_xor_sync(0xffffffffu, v, o);
    return v;
}
__device__ __forceinline__ float warpMax(float v){
#pragma unroll
    for (int o = 16; o; o >>= 1) v = fmaxf(v, __shfl_xor_sync(0xffffffffu, v, o));
    return v;
}
__device__ float blockSum(float v){
    __shared__ float s[9];
    __syncthreads();
    int lane = threadIdx.x & 31, w = threadIdx.x >> 5;
    v = warpSum(v);
    if (lane == 0) s[w] = v;
    __syncthreads();
    if (w == 0){
        float x = (lane < (int)(blockDim.x >> 5)) ? s[lane] : 0.f;
        x = warpSum(x);
        if (lane == 0) s[8] = x;
    }
    __syncthreads();
    return s[8];
}
__device__ float blockMax(float v){
    __shared__ float s[9];
    __syncthreads();
    int lane = threadIdx.x & 31, w = threadIdx.x >> 5;
    v = warpMax(v);
    if (lane == 0) s[w] = v;
    __syncthreads();
    if (w == 0){
        float x = (lane < (int)(blockDim.x >> 5)) ? s[lane] : -INFINITY;
        x = warpMax(x);
        if (lane == 0) s[8] = x;
    }
    __syncthreads();
    return s[8];
}

// ---------------- embedding ----------------
__global__ void embed_kernel(const int* __restrict__ x,
                             const float* __restrict__ tok,
                             const float* __restrict__ pos){
    int t  = blockIdx.x;
    int id = x[t];
    const float* tr = tok + (size_t)id * DD;
    const float* pr = pos + (size_t)t  * DD;
    for (int d = threadIdx.x; d < DD; d += blockDim.x)
        g_h[t*DD + d] = tr[d] + pr[d];
}

// ---------------- layernorm ----------------
__global__ void ln_kernel(const float* __restrict__ in, float* __restrict__ out,
                          const float* __restrict__ g, const float* __restrict__ b){
    __shared__ float row[DD];
    int t = blockIdx.x;
    const float* r = in + (size_t)t * DD;
    float s = 0.f;
    for (int d = threadIdx.x; d < DD; d += blockDim.x){ float v = r[d]; row[d] = v; s += v; }
    s = blockSum(s);
    float mean = s * (1.f / DD);
    float q = 0.f;
    for (int d = threadIdx.x; d < DD; d += blockDim.x){ float v = row[d] - mean; q += v*v; }
    q = blockSum(q);
    float rstd = rsqrtf(q * (1.f / DD) + 1e-5f);
    for (int d = threadIdx.x; d < DD; d += blockDim.x)
        out[t*DD + d] = (row[d] - mean) * rstd * g[d] + b[d];
}

// ================== bf16-split tensor-core GEMM ==================
#define ROWB 80
#define STAGE_B 40960
#define G_SMEM (2*STAGE_B)

template<int BIASF, int GELUF, int RESF>
__global__ __launch_bounds__(256, 1)
void gemm_mma(const float* __restrict__ A, const float* __restrict__ B,
              const float* __restrict__ bias, const float* __restrict__ res,
              float* __restrict__ C, int M, int N, int K)
{
    extern __shared__ char smem[];
    const uint32_t sb = smem_u32(smem);
    const int tid = threadIdx.x, wid = tid >> 5, lane = tid & 31;
    const int m0 = blockIdx.x << 7, n0 = blockIdx.y << 7;
    const int wm = (wid >> 2) << 6;
    const int wn = (wid & 3) << 5;

    const int lrow = tid >> 1;
    const int j0   = (tid & 1) << 2;
    const float* Ap = A + (size_t)(m0 + lrow) * K + (j0 << 2);
    const float* Bp = B + (size_t)(n0 + lrow) * K + (j0 << 2);
    const uint32_t stsA = sb + lrow * ROWB + (j0 << 3);
    const uint32_t stsB = stsA + 2 * 10240;

    float acc[4][4][4];
#pragma unroll
    for (int i = 0; i < 4; i++)
#pragma unroll
        for (int j = 0; j < 4; j++)
#pragma unroll
            for (int k = 0; k < 4; k++) acc[i][j][k] = 0.f;

    const int NC = K >> 5;
    float4 aR[4], bR[4];

#pragma unroll
    for (int j = 0; j < 4; j++){
        aR[j] = *(const float4*)(Ap + (j << 2));
        bR[j] = *(const float4*)(Bp + (j << 2));
    }
#pragma unroll
    for (int j = 0; j < 4; j++){
        uint32_t h0 = packbf(aR[j].x, aR[j].y), h1 = packbf(aR[j].z, aR[j].w);
        float l0 = aR[j].x - __uint_as_float(h0 << 16);
        float l1 = aR[j].y - __uint_as_float(h0 & 0xffff0000u);
        float l2 = aR[j].z - __uint_as_float(h1 << 16);
        float l3 = aR[j].w - __uint_as_float(h1 & 0xffff0000u);
        asm volatile("st.shared.v2.b32 [%0], {%1,%2};" :: "r"(stsA + (j << 3)), "r"(h0), "r"(h1) : "memory");
        asm volatile("st.shared.v2.b32 [%0], {%1,%2};" :: "r"(stsA + 10240 + (j << 3)),
                     "r"(packbf(l0, l1)), "r"(packbf(l2, l3)) : "memory");
        uint32_t g0 = packbf(bR[j].x, bR[j].y), g1 = packbf(bR[j].z, bR[j].w);
        float m0f = bR[j].x - __uint_as_float(g0 << 16);
        float m1f = bR[j].y - __uint_as_float(g0 & 0xffff0000u);
        float m2f = bR[j].z - __uint_as_float(g1 << 16);
        float m3f = bR[j].w - __uint_as_float(g1 & 0xffff0000u);
        asm volatile("st.shared.v2.b32 [%0], {%1,%2};" :: "r"(stsB + (j << 3)), "r"(g0), "r"(g1) : "memory");
        asm volatile("st.shared.v2.b32 [%0], {%1,%2};" :: "r"(stsB + 10240 + (j << 3)),
                     "r"(packbf(m0f, m1f)), "r"(packbf(m2f, m3f)) : "memory");
    }
    __syncthreads();

    const int g  = lane >> 3, lr = lane & 7;
    const int arow_off = ((g & 1) << 3) + lr;
    const int akb      = (g >> 1) << 4;
    const int brow_off = ((g >> 1) << 3) + lr;
    const int bkb      = (g & 1) << 4;

    for (int c = 0; c < NC; c++){
        const uint32_t st = sb + (c & 1) * STAGE_B;

        if (c + 1 < NC){
#pragma unroll
            for (int j = 0; j < 4; j++){
                aR[j] = *(const float4*)(Ap + (size_t)(c + 1) * 32 + (j << 2));
                bR[j] = *(const float4*)(Bp + (size_t)(c + 1) * 32 + (j << 2));
            }
        }

#pragma unroll
        for (int h = 0; h < 2; h++){
            uint32_t Ah[4][4], Al[4][4], Bh[4][2], Bl[4][2];
#pragma unroll
            for (int mt = 0; mt < 4; mt++){
                uint32_t ad = st + (uint32_t)((wm + (mt << 4) + arow_off) * ROWB + (h << 5) + akb);
                ldsm4(Ah[mt][0], Ah[mt][1], Ah[mt][2], Ah[mt][3], ad);
                ldsm4(Al[mt][0], Al[mt][1], Al[mt][2], Al[mt][3], ad + 10240);
            }
#pragma unroll
            for (int nt2 = 0; nt2 < 2; nt2++){
                uint32_t bd = st + 20480 + (uint32_t)((wn + (nt2 << 4) + brow_off) * ROWB + (h << 5) + bkb);
                uint32_t r0, r1, r2, r3;
                ldsm4(r0, r1, r2, r3, bd);
                Bh[2*nt2][0] = r0; Bh[2*nt2][1] = r1; Bh[2*nt2+1][0] = r2; Bh[2*nt2+1][1] = r3;
                ldsm4(r0, r1, r2, r3, bd + 10240);
                Bl[2*nt2][0] = r0; Bl[2*nt2][1] = r1; Bl[2*nt2+1][0] = r2; Bl[2*nt2+1][1] = r3;
            }
#pragma unroll
            for (int mt = 0; mt < 4; mt++)
#pragma unroll
                for (int nt = 0; nt < 4; nt++){
                    mma16816(acc[mt][nt], Ah[mt], Bh[nt]);
                    mma16816(acc[mt][nt], Ah[mt], Bl[nt]);
                    mma16816(acc[mt][nt], Al[mt], Bh[nt]);
                }
        }

        if (c + 1 < NC){
            const uint32_t dsA = stsA + ((c + 1) & 1) * STAGE_B;
            const uint32_t dsB = stsB + ((c + 1) & 1) * STAGE_B;
#pragma unroll
            for (int j = 0; j < 4; j++){
                uint32_t h0 = packbf(aR[j].x, aR[j].y), h1 = packbf(aR[j].z, aR[j].w);
                float l0 = aR[j].x - __uint_as_float(h0 << 16);
                float l1 = aR[j].y - __uint_as_float(h0 & 0xffff0000u);
                float l2 = aR[j].z - __uint_as_float(h1 << 16);
                float l3 = aR[j].w - __uint_as_float(h1 & 0xffff0000u);
                asm volatile("st.shared.v2.b32 [%0], {%1,%2};" :: "r"(dsA + (j << 3)), "r"(h0), "r"(h1) : "memory");
                asm volatile("st.shared.v2.b32 [%0], {%1,%2};" :: "r"(dsA + 10240 + (j << 3)),
                             "r"(packbf(l0, l1)), "r"(packbf(l2, l3)) : "memory");
                uint32_t g0 = packbf(bR[j].x, bR[j].y), g1 = packbf(bR[j].z, bR[j].w);
                float q0 = bR[j].x - __uint_as_float(g0 << 16);
                float q1 = bR[j].y - __uint_as_float(g0 & 0xffff0000u);
                float q2 = bR[j].z - __uint_as_float(g1 << 16);
                float q3 = bR[j].w - __uint_as_float(g1 & 0xffff0000u);
                asm volatile("st.shared.v2.b32 [%0], {%1,%2};" :: "r"(dsB + (j << 3)), "r"(g0), "r"(g1) : "memory");
                asm volatile("st.shared.v2.b32 [%0], {%1,%2};" :: "r"(dsB + 10240 + (j << 3)),
                             "r"(packbf(q0, q1)), "r"(packbf(q2, q3)) : "memory");
            }
        }
        __syncthreads();
    }

    const int qr = lane >> 2, qc = lane & 3;
#pragma unroll
    for (int mt = 0; mt < 4; mt++){
#pragma unroll
        for (int p = 0; p < 2; p++){
            int m = m0 + wm + (mt << 4) + qr + (p << 3);
            size_t rowbase = (size_t)m * N;
#pragma unroll
            for (int nt = 0; nt < 4; nt++){
                int n = n0 + wn + (nt << 3) + (qc << 1);
                float v0 = acc[mt][nt][2*p], v1 = acc[mt][nt][2*p + 1];
                if (BIASF){ v0 += bias[n]; v1 += bias[n + 1]; }
                if (GELUF){
                    v0 = 0.5f * v0 * (1.f + erff(v0 * 0.70710678118654752f));
                    v1 = 0.5f * v1 * (1.f + erff(v1 * 0.70710678118654752f));
                }
                if (RESF){
                    float2 rr = *(const float2*)&res[rowbase + n];
                    v0 += rr.x; v1 += rr.y;
                }
                *(float2*)&C[rowbase + n] = make_float2(v0, v1);
            }
        }
    }
}

// ================== tensor-core flash attention ==================
// 128 q-rows per block (8 warps x 16), 64-key tiles, bf16-split mma.
// smem per stage: Khi[64][72], Klo, Vhi, Vlo  (72 bf16 = 144B rows)
#define AROWB 144
#define KOFF_LO  9216
#define VOFF_HI 18432
#define VOFF_LO 27648
#define ATT_STAGE 36864
#define ATT_SMEM (2*ATT_STAGE)

__global__ __launch_bounds__(256)
void attn_tc(){
    extern __shared__ char smc[];
    const uint32_t sb = smem_u32(smc);
    const int tid = threadIdx.x, wid = tid >> 5, lane = tid & 31;
    const int qb = gridDim.x - 1 - (int)blockIdx.x;
    const int hh = blockIdx.y;
    const int q0 = qb << 7;
    const int wq = q0 + (wid << 4);         // warp's first q row

    // ---- Q fragments direct from global (scaled by 0.125*log2e), hi/lo split ----
    const float SCL = 0.125f * 1.4426950408889634f;
    uint32_t qh[4][4], ql[4][4];
    {
        int r0 = wq + (lane >> 2);
        int c0 = (lane & 3) << 1;
        const float* base = g_qkv + hh * DHH;
#pragma unroll
        for (int kt = 0; kt < 4; kt++){
#pragma unroll
            for (int rr = 0; rr < 2; rr++){
                const float* p = base + (size_t)(r0 + (rr << 3)) * QKV3 + (kt << 4) + c0;
                float2 f0 = *(const float2*)p;
                float2 f1 = *(const float2*)(p + 8);
                float x0 = f0.x*SCL, x1 = f0.y*SCL, x2 = f1.x*SCL, x3 = f1.y*SCL;
                uint32_t h0 = packbf(x0, x1), h1 = packbf(x2, x3);
                qh[kt][rr]     = h0;
                qh[kt][rr + 2] = h1;
                ql[kt][rr]     = packbf(x0 - __uint_as_float(h0 << 16),
                                        x1 - __uint_as_float(h0 & 0xffff0000u));
                ql[kt][rr + 2] = packbf(x2 - __uint_as_float(h1 << 16),
                                        x3 - __uint_as_float(h1 & 0xffff0000u));
            }
        }
    }

    float o[8][4];
#pragma unroll
    for (int i = 0; i < 8; i++){ o[i][0]=0.f; o[i][1]=0.f; o[i][2]=0.f; o[i][3]=0.f; }
    float mr0 = -INFINITY, mr1 = -INFINITY, lr0 = 0.f, lr1 = 0.f;

    const int jmax = (q0 >> 6) + 1;

    // loader mapping: row = tid>>2 (0..63), col start = (tid&3)*16 floats
    const int ldr = tid >> 2;
    const int ldc = (tid & 3) << 4;
    const float* kgp = g_qkv + (size_t)ldr * QKV3 + DD     + hh * DHH + ldc;
    const float* vgp = g_qkv + (size_t)ldr * QKV3 + 2 * DD + hh * DHH + ldc;

    float4 kf[4], vf[4];
#pragma unroll
    for (int t = 0; t < 4; t++){
        kf[t] = *(const float4*)(kgp + (t << 2));
        vf[t] = *(const float4*)(vgp + (t << 2));
    }

    // ldmatrix addressing pieces
    const int g  = lane >> 3, lr8 = lane & 7;
    const int brow_off = ((g >> 1) << 3) + lr8;
    const int bkb      = (g & 1) << 4;
    const uint32_t sts_base = (uint32_t)(ldr * AROWB + (ldc << 1));

    for (int j = 0; j <= jmax; j++){
        const uint32_t st = sb + (j & 1) * ATT_STAGE;
        // store current regs (tile j) to stage j&1
        {
            uint32_t h[4], l[4];
#pragma unroll
            for (int t = 0; t < 4; t++){
                uint32_t a = packbf(kf[t].x, kf[t].y), b = packbf(kf[t].z, kf[t].w);
                h[t] = 0; // reuse below
                h[t] = a;  l[t] = b;
            }
            // K hi
            *(uint4*)(smc + (st - sb) + sts_base) =
                make_uint4(packbf(kf[0].x,kf[0].y), packbf(kf[0].z,kf[0].w),
                           packbf(kf[1].x,kf[1].y), packbf(kf[1].z,kf[1].w));
            *(uint4*)(smc + (st - sb) + sts_base + 16) =
                make_uint4(packbf(kf[2].x,kf[2].y), packbf(kf[2].z,kf[2].w),
                           packbf(kf[3].x,kf[3].y), packbf(kf[3].z,kf[3].w));
            // K lo
            uint32_t kl0[4];
#pragma unroll
            for (int t = 0; t < 4; t++){
                uint32_t hh0 = packbf(kf[t].x, kf[t].y), hh1 = packbf(kf[t].z, kf[t].w);
                kl0[t] = packbf(kf[t].x - __uint_as_float(hh0 << 16),
                                kf[t].y - __uint_as_float(hh0 & 0xffff0000u));
                l[t]   = packbf(kf[t].z - __uint_as_float(hh1 << 16),
                                kf[t].w - __uint_as_float(hh1 & 0xffff0000u));
            }
            *(uint4*)(smc + (st - sb) + KOFF_LO + sts_base)      = make_uint4(kl0[0], l[0], kl0[1], l[1]);
            *(uint4*)(smc + (st - sb) + KOFF_LO + sts_base + 16) = make_uint4(kl0[2], l[2], kl0[3], l[3]);
            // V hi
            *(uint4*)(smc + (st - sb) + VOFF_HI + sts_base) =
                make_uint4(packbf(vf[0].x,vf[0].y), packbf(vf[0].z,vf[0].w),
                           packbf(vf[1].x,vf[1].y), packbf(vf[1].z,vf[1].w));
            *(uint4*)(smc + (st - sb) + VOFF_HI + sts_base + 16) =
                make_uint4(packbf(vf[2].x,vf[2].y), packbf(vf[2].z,vf[2].w),
                           packbf(vf[3].x,vf[3].y), packbf(vf[3].z,vf[3].w));
            // V lo
            uint32_t vl0[4], vl1[4];
#pragma unroll
            for (int t = 0; t < 4; t++){
                uint32_t hh0 = packbf(vf[t].x, vf[t].y), hh1 = packbf(vf[t].z, vf[t].w);
                vl0[t] = packbf(vf[t].x - __uint_as_float(hh0 << 16),
                                vf[t].y - __uint_as_float(hh0 & 0xffff0000u));
                vl1[t] = packbf(vf[t].z - __uint_as_float(hh1 << 16),
                                vf[t].w - __uint_as_float(hh1 & 0xffff0000u));
            }
            *(uint4*)(smc + (st - sb) + VOFF_LO + sts_base)      = make_uint4(vl0[0], vl1[0], vl0[1], vl1[1]);
            *(uint4*)(smc + (st - sb) + VOFF_LO + sts_base + 16) = make_uint4(vl0[2], vl1[2], vl0[3], vl1[3]);
        }
        __syncthreads();

        // prefetch tile j+1
        if (j < jmax){
            const float* kp2 = kgp + (size_t)((j + 1) << 6) * QKV3;
            const float* vp2 = vgp + (size_t)((j + 1) << 6) * QKV3;
#pragma unroll
            for (int t = 0; t < 4; t++){
                kf[t] = *(const float4*)(kp2 + (t << 2));
                vf[t] = *(const float4*)(vp2 + (t << 2));
            }
        }

        if ((j << 6) <= wq + 15){
            // ---- S = Q K^T (bf16 3-product) ----
            float s[8][4];
#pragma unroll
            for (int i = 0; i < 8; i++){ s[i][0]=0.f; s[i][1]=0.f; s[i][2]=0.f; s[i][3]=0.f; }
#pragma unroll
            for (int ks = 0; ks < 4; ks++){
                uint32_t kh[8][2], kl[8][2];
#pragma unroll
                for (int nt2 = 0; nt2 < 4; nt2++){
                    uint32_t ad = st + (uint32_t)(((nt2 << 4) + brow_off) * AROWB + (ks << 5) + bkb);
                    uint32_t r0, r1, r2, r3;
                    ldsm4(r0, r1, r2, r3, ad);
                    kh[2*nt2][0]=r0; kh[2*nt2][1]=r1; kh[2*nt2+1][0]=r2; kh[2*nt2+1][1]=r3;
                    ldsm4(r0, r1, r2, r3, ad + KOFF_LO);
                    kl[2*nt2][0]=r0; kl[2*nt2][1]=r1; kl[2*nt2+1][0]=r2; kl[2*nt2+1][1]=r3;
                }
#pragma unroll
                for (int nt = 0; nt < 8; nt++){
                    mma16816(s[nt], qh[ks], kh[nt]);
                    mma16816(s[nt], qh[ks], kl[nt]);
                    mma16816(s[nt], ql[ks], kh[nt]);
                }
            }
            // ---- causal mask ----
            if ((j << 6) + 63 > wq){
                int qr0 = wq + (lane >> 2);
#pragma unroll
                for (int nt = 0; nt < 8; nt++){
                    int kp = (j << 6) + (nt << 3) + ((lane & 3) << 1);
#pragma unroll
                    for (int e = 0; e < 4; e++){
                        int kpos = kp + (e & 1);
                        int qrow = qr0 + ((e >> 1) << 3);
                        if (kpos > qrow) s[nt][e] = -INFINITY;
                    }
                }
            }
            // ---- online softmax (log2 domain) ----
            float mx0 = -INFINITY, mx1 = -INFINITY;
#pragma unroll
            for (int nt = 0; nt < 8; nt++){
                mx0 = fmaxf(mx0, fmaxf(s[nt][0], s[nt][1]));
                mx1 = fmaxf(mx1, fmaxf(s[nt][2], s[nt][3]));
            }
            mx0 = fmaxf(mx0, __shfl_xor_sync(0xffffffffu, mx0, 1));
            mx0 = fmaxf(mx0, __shfl_xor_sync(0xffffffffu, mx0, 2));
            mx1 = fmaxf(mx1, __shfl_xor_sync(0xffffffffu, mx1, 1));
            mx1 = fmaxf(mx1, __shfl_xor_sync(0xffffffffu, mx1, 2));
            float mn0 = fmaxf(mr0, mx0), mn1 = fmaxf(mr1, mx1);
            float a0 = ex2f(mr0 - mn0), a1 = ex2f(mr1 - mn1);
            mr0 = mn0; mr1 = mn1;
            lr0 *= a0; lr1 *= a1;
#pragma unroll
            for (int nt = 0; nt < 8; nt++){
                o[nt][0] *= a0; o[nt][1] *= a0; o[nt][2] *= a1; o[nt][3] *= a1;
            }
            float sum0 = 0.f, sum1 = 0.f;
#pragma unroll
            for (int nt = 0; nt < 8; nt++){
                s[nt][0] = ex2f(s[nt][0] - mn0);
                s[nt][1] = ex2f(s[nt][1] - mn0);
                s[nt][2] = ex2f(s[nt][2] - mn1);
                s[nt][3] = ex2f(s[nt][3] - mn1);
                sum0 += s[nt][0] + s[nt][1];
                sum1 += s[nt][2] + s[nt][3];
            }
            lr0 += sum0; lr1 += sum1;
            // ---- O += P V (bf16 3-product, P frags built in-register) ----
#pragma unroll
            for (int kt = 0; kt < 4; kt++){
                uint32_t ph[4], pl[4];
                {
                    float p00 = s[2*kt][0],   p01 = s[2*kt][1];
                    float p10 = s[2*kt][2],   p11 = s[2*kt][3];
                    float p20 = s[2*kt+1][0], p21 = s[2*kt+1][1];
                    float p30 = s[2*kt+1][2], p31 = s[2*kt+1][3];
                    ph[0] = packbf(p00, p01); ph[1] = packbf(p10, p11);
                    ph[2] = packbf(p20, p21); ph[3] = packbf(p30, p31);
                    pl[0] = packbf(p00 - __uint_as_float(ph[0] << 16),
                                   p01 - __uint_as_float(ph[0] & 0xffff0000u));
                    pl[1] = packbf(p10 - __uint_as_float(ph[1] << 16),
                                   p11 - __uint_as_float(ph[1] & 0xffff0000u));
                    pl[2] = packbf(p20 - __uint_as_float(ph[2] << 16),
                                   p21 - __uint_as_float(ph[2] & 0xffff0000u));
                    pl[3] = packbf(p30 - __uint_as_float(ph[3] << 16),
                                   p31 - __uint_as_float(ph[3] & 0xffff0000u));
                }
#pragma unroll
                for (int nt2 = 0; nt2 < 4; nt2++){
                    uint32_t va = st + VOFF_HI +
                        (uint32_t)(((kt << 4) + (lane & 15)) * AROWB + (((nt2 << 4) + ((lane >> 4) << 3)) << 1));
                    uint32_t r0, r1, r2, r3;
                    ldsm4t(r0, r1, r2, r3, va);
                    uint32_t bh0[2] = {r0, r1}, bh1[2] = {r2, r3};
                    ldsm4t(r0, r1, r2, r3, va + (VOFF_LO - VOFF_HI));
                    uint32_t bl0[2] = {r0, r1}, bl1[2] = {r2, r3};
                    mma16816(o[2*nt2],   ph, bh0);
                    mma16816(o[2*nt2],   pl, bh0);
                    mma16816(o[2*nt2],   ph, bl0);
                    mma16816(o[2*nt2+1], ph, bh1);
                    mma16816(o[2*nt2+1], pl, bh1);
                    mma16816(o[2*nt2+1], ph, bl1);
                }
            }
        }
        __syncthreads();
    }

    // ---- finalize ----
    lr0 += __shfl_xor_sync(0xffffffffu, lr0, 1);
    lr0 += __shfl_xor_sync(0xffffffffu, lr0, 2);
    lr1 += __shfl_xor_sync(0xffffffffu, lr1, 1);
    lr1 += __shfl_xor_sync(0xffffffffu, lr1, 2);
    float inv0 = 1.f / lr0, inv1 = 1.f / lr1;
    int qrow = wq + (lane >> 2);
    int cc = hh * DHH + ((lane & 3) << 1);
#pragma unroll
    for (int nt = 0; nt < 8; nt++){
        *(float2*)&g_ctx[(size_t)qrow * DD + cc + (nt << 3)] =
            make_float2(o[nt][0] * inv0, o[nt][1] * inv0);
        *(float2*)&g_ctx[(size_t)(qrow + 8) * DD + cc + (nt << 3)] =
            make_float2(o[nt][2] * inv1, o[nt][3] * inv1);
    }
}

// ---------------- loss ----------------
__global__ void row_lse_kernel(const float* __restrict__ logits, const int* __restrict__ tgt){
    int t = blockIdx.x;
    const float* row = logits + (size_t)t * VV;
    float mx = -INFINITY;
    for (int i = threadIdx.x; i < VV; i += blockDim.x) mx = fmaxf(mx, row[i]);
    mx = blockMax(mx);
    float s = 0.f;
    for (int i = threadIdx.x; i < VV; i += blockDim.x) s += expf(row[i] - mx);
    s = blockSum(s);
    if (threadIdx.x == 0){
        int tg = tgt[t];
        float lse = mx + logf(s);
        float nll = lse - row[tg];
        g_nll[t] = (tg != 0) ? nll : 0.f;
        g_val[t] = (tg != 0) ? 1.f : 0.f;
    }
}

__global__ void loss_reduce_kernel(float* __restrict__ out_loss){
    float a = 0.f, b = 0.f;
    for (int t = threadIdx.x; t < TT; t += blockDim.x){ a += g_nll[t]; b += g_val[t]; }
    a = blockSum(a);
    b = blockSum(b);
    if (threadIdx.x == 0) *out_loss = a / fmaxf(b, 1.f);
}

// ---------------- launch ----------------
extern "C" void kernel_launch(void* const* d_in, const int* in_sizes, int n_in,
                              void* d_out, int out_size){
    (void)in_sizes; (void)n_in;
    const int*   x     = (const int*)  d_in[0];
    const int*   tgt   = (const int*)  d_in[1];
    const float* tok   = (const float*)d_in[2];
    const float* pos   = (const float*)d_in[3];
    const float* Wqkv  = (const float*)d_in[4];
    const float* Wo    = (const float*)d_in[5];
    const float* ln1g  = (const float*)d_in[6];
    const float* ln1b  = (const float*)d_in[7];
    const float* ln2g  = (const float*)d_in[8];
    const float* ln2b  = (const float*)d_in[9];
    const float* W1    = (const float*)d_in[10];
    const float* b1    = (const float*)d_in[11];
    const float* W2    = (const float*)d_in[12];
    const float* b2    = (const float*)d_in[13];
    const float* lnfg  = (const float*)d_in[14];
    const float* lnfb  = (const float*)d_in[15];
    float* out = (float*)d_out;

    float *ph, *phn, *pqkv, *pctx, *pff;
    cudaGetSymbolAddress((void**)&ph,   g_h);
    cudaGetSymbolAddress((void**)&phn,  g_hn);
    cudaGetSymbolAddress((void**)&pqkv, g_qkv);
    cudaGetSymbolAddress((void**)&pctx, g_ctx);
    cudaGetSymbolAddress((void**)&pff,  g_ff);

    cudaFuncSetAttribute(gemm_mma<0,0,0>, cudaFuncAttributeMaxDynamicSharedMemorySize, G_SMEM);
    cudaFuncSetAttribute(gemm_mma<0,0,1>, cudaFuncAttributeMaxDynamicSharedMemorySize, G_SMEM);
    cudaFuncSetAttribute(gemm_mma<1,1,0>, cudaFuncAttributeMaxDynamicSharedMemorySize, G_SMEM);
    cudaFuncSetAttribute(gemm_mma<1,0,1>, cudaFuncAttributeMaxDynamicSharedMemorySize, G_SMEM);
    cudaFuncSetAttribute(attn_tc, cudaFuncAttributeMaxDynamicSharedMemorySize, ATT_SMEM);

    embed_kernel<<<TT, 256>>>(x, tok, pos);

    for (int l = 0; l < LL; l++){
        ln_kernel<<<TT, 256>>>(ph, phn, ln1g + l*DD, ln1b + l*DD);
        gemm_mma<0,0,0><<<dim3(TT/128, QKV3/128), 256, G_SMEM>>>(
            phn, Wqkv + (size_t)l*QKV3*DD, nullptr, nullptr, pqkv, TT, QKV3, DD);
        attn_tc<<<dim3(TT/128, HH), 256, ATT_SMEM>>>();
        gemm_mma<0,0,1><<<dim3(TT/128, DD/128), 256, G_SMEM>>>(
            pctx, Wo + (size_t)l*DD*DD, nullptr, ph, ph, TT, DD, DD);
        ln_kernel<<<TT, 256>>>(ph, phn, ln2g + l*DD, ln2b + l*DD);
        gemm_mma<1,1,0><<<dim3(TT/128, FFD/128), 256, G_SMEM>>>(
            phn, W1 + (size_t)l*FFD*DD, b1 + (size_t)l*FFD, nullptr, pff, TT, FFD, DD);
        gemm_mma<1,0,1><<<dim3(TT/128, DD/128), 256, G_SMEM>>>(
            pff, W2 + (size_t)l*DD*FFD, b2 + (size_t)l*DD, ph, ph, TT, DD, FFD);
    }

    ln_kernel<<<TT, 256>>>(ph, phn, lnfg, lnfb);
    gemm_mma<0,0,0><<<dim3(TT/128, VV/128), 256, G_SMEM>>>(
        phn, tok, nullptr, nullptr, out, TT, VV, DD);

    row_lse_kernel<<<TT, 256>>>(out, tgt);
    if (out_size > TT * VV)
        loss_reduce_kernel<<<1, 256>>>(out + (size_t)TT * VV);
}

// round 7
// speedup vs baseline: 2.6200x; 1.0654x over previous
#include <cuda_runtime.h>
#include <cuda_bf16.h>
#include <cuda_fp16.h>
#include <math.h>
#include <stdint.h>

// Problem constants
#define TT   2048
#define DD   768
#define HH   12
#define DHH  64
#define LL   6
#define FFD  3072
#define VV   32000
#define QKV3 (3*DD)

// ---------------- scratch ----------------
__device__ float g_h  [TT*DD];
__device__ float g_hn [TT*DD];
__device__ float g_qkv[TT*QKV3];
__device__ float g_ctx[TT*DD];
__device__ float g_ff [TT*FFD];
__device__ float g_nll[TT];
__device__ float g_val[TT];

// ---------------- helpers ----------------
__device__ __forceinline__ uint32_t smem_u32(const void* p){
    uint32_t a;
    asm("{ .reg .u64 t; cvta.to.shared.u64 t, %1; cvt.u32.u64 %0, t; }" : "=r"(a) : "l"(p));
    return a;
}
__device__ __forceinline__ uint32_t packbf(float x0, float x1){
    uint32_t r;
    asm("cvt.rn.bf16x2.f32 %0, %1, %2;" : "=r"(r) : "f"(x1), "f"(x0));
    return r;
}
__device__ __forceinline__ uint32_t packhf(float x0, float x1){
    uint32_t r;
    asm("cvt.rn.f16x2.f32 %0, %1, %2;" : "=r"(r) : "f"(x1), "f"(x0));
    return r;
}
__device__ __forceinline__ float h2f_lo(uint32_t p){
    float f; asm("{ .reg .b16 h, dummy; mov.b32 {h, dummy}, %1; cvt.f32.f16 %0, h; }" : "=f"(f) : "r"(p));
    return f;
}
__device__ __forceinline__ float h2f_hi(uint32_t p){
    float f; asm("{ .reg .b16 h, dummy; mov.b32 {dummy, h}, %1; cvt.f32.f16 %0, h; }" : "=f"(f) : "r"(p));
    return f;
}
__device__ __forceinline__ float ex2f(float x){
    float y; asm("ex2.approx.f32 %0, %1;" : "=f"(y) : "f"(x)); return y;
}
__device__ __forceinline__ void ldsm4(uint32_t &r0, uint32_t &r1, uint32_t &r2, uint32_t &r3,
                                      uint32_t addr){
    asm volatile("ldmatrix.sync.aligned.m8n8.x4.shared.b16 {%0,%1,%2,%3}, [%4];"
        : "=r"(r0), "=r"(r1), "=r"(r2), "=r"(r3) : "r"(addr));
}
__device__ __forceinline__ void ldsm4t(uint32_t &r0, uint32_t &r1, uint32_t &r2, uint32_t &r3,
                                       uint32_t addr){
    asm volatile("ldmatrix.sync.aligned.m8n8.x4.trans.shared.b16 {%0,%1,%2,%3}, [%4];"
        : "=r"(r0), "=r"(r1), "=r"(r2), "=r"(r3) : "r"(addr));
}
__device__ __forceinline__ void mma16816(float* d, const uint32_t* a, const uint32_t* b){
    asm volatile("mma.sync.aligned.m16n8k16.row.col.f32.bf16.bf16.f32 "
        "{%0,%1,%2,%3}, {%4,%5,%6,%7}, {%8,%9}, {%0,%1,%2,%3};"
        : "+f"(d[0]), "+f"(d[1]), "+f"(d[2]), "+f"(d[3])
        : "r"(a[0]), "r"(a[1]), "r"(a[2]), "r"(a[3]), "r"(b[0]), "r"(b[1]));
}
__device__ __forceinline__ void mma16816h(float* d, const uint32_t* a, const uint32_t* b){
    asm volatile("mma.sync.aligned.m16n8k16.row.col.f32.f16.f16.f32 "
        "{%0,%1,%2,%3}, {%4,%5,%6,%7}, {%8,%9}, {%0,%1,%2,%3};"
        : "+f"(d[0]), "+f"(d[1]), "+f"(d[2]), "+f"(d[3])
        : "r"(a[0]), "r"(a[1]), "r"(a[2]), "r"(a[3]), "r"(b[0]), "r"(b[1]));
}

// ---------------- reductions ----------------
__device__ __forceinline__ float warpSum(float v){
#pragma unroll
    for (int o = 16; o; o >>= 1) v += __shfl_xor_sync(0xffffffffu, v, o);
    return v;
}
__device__ __forceinline__ float warpMax(float v){
#pragma unroll
    for (int o = 16; o; o >>= 1) v = fmaxf(v, __shfl_xor_sync(0xffffffffu, v, o));
    return v;
}
__device__ float blockSum(float v){
    __shared__ float s[9];
    __syncthreads();
    int lane = threadIdx.x & 31, w = threadIdx.x >> 5;
    v = warpSum(v);
    if (lane == 0) s[w] = v;
    __syncthreads();
    if (w == 0){
        float x = (lane < (int)(blockDim.x >> 5)) ? s[lane] : 0.f;
        x = warpSum(x);
        if (lane == 0) s[8] = x;
    }
    __syncthreads();
    return s[8];
}
__device__ float blockMax(float v){
    __shared__ float s[9];
    __syncthreads();
    int lane = threadIdx.x & 31, w = threadIdx.x >> 5;
    v = warpMax(v);
    if (lane == 0) s[w] = v;
    __syncthreads();
    if (w == 0){
        float x = (lane < (int)(blockDim.x >> 5)) ? s[lane] : -INFINITY;
        x = warpMax(x);
        if (lane == 0) s[8] = x;
    }
    __syncthreads();
    return s[8];
}

// ---------------- embedding ----------------
__global__ void embed_kernel(const int* __restrict__ x,
                             const float* __restrict__ tok,
                             const float* __restrict__ pos){
    int t  = blockIdx.x;
    int id = x[t];
    const float* tr = tok + (size_t)id * DD;
    const float* pr = pos + (size_t)t  * DD;
    for (int d = threadIdx.x; d < DD; d += blockDim.x)
        g_h[t*DD + d] = tr[d] + pr[d];
}

// ---------------- layernorm ----------------
__global__ void ln_kernel(const float* __restrict__ in, float* __restrict__ out,
                          const float* __restrict__ g, const float* __restrict__ b){
    __shared__ float row[DD];
    int t = blockIdx.x;
    const float* r = in + (size_t)t * DD;
    float s = 0.f;
    for (int d = threadIdx.x; d < DD; d += blockDim.x){ float v = r[d]; row[d] = v; s += v; }
    s = blockSum(s);
    float mean = s * (1.f / DD);
    float q = 0.f;
    for (int d = threadIdx.x; d < DD; d += blockDim.x){ float v = row[d] - mean; q += v*v; }
    q = blockSum(q);
    float rstd = rsqrtf(q * (1.f / DD) + 1e-5f);
    for (int d = threadIdx.x; d < DD; d += blockDim.x)
        out[t*DD + d] = (row[d] - mean) * rstd * g[d] + b[d];
}

// ================== split tensor-core GEMM, 3-stage pipeline ==================
// C[M,N] = A[M,K] @ B[N,K]^T (+bias)(+gelu)(+res), fp32 in/out.
// 128x128 CTA tile, BK=32, 8 warps (2x4), warp tile 64x32.
// PREC=0: bf16 3-product (AhBh + AhBl + AlBh), residual ~2^-18.
// PREC=1: fp16 2-product (A split hi/lo, B single fp16), error ~2^-11 from B.
// stage layout: Ahi[10240] Alo[10240] Bhi[10240] Blo[10240] = 40960 B; 3 stages.
#define ROWB 80
#define STAGE_B 40960
#define G_SMEM (3*STAGE_B)

// convert+store one chunk held in registers into a stage
template<int PREC>
__device__ __forceinline__ void sts_chunk(uint32_t dsA, uint32_t dsB,
                                          const float4* aR, const float4* bR){
#pragma unroll
    for (int j = 0; j < 4; j++){
        if (PREC == 0){
            uint32_t h0 = packbf(aR[j].x, aR[j].y), h1 = packbf(aR[j].z, aR[j].w);
            float l0 = aR[j].x - __uint_as_float(h0 << 16);
            float l1 = aR[j].y - __uint_as_float(h0 & 0xffff0000u);
            float l2 = aR[j].z - __uint_as_float(h1 << 16);
            float l3 = aR[j].w - __uint_as_float(h1 & 0xffff0000u);
            asm volatile("st.shared.v2.b32 [%0], {%1,%2};" :: "r"(dsA + (j << 3)), "r"(h0), "r"(h1) : "memory");
            asm volatile("st.shared.v2.b32 [%0], {%1,%2};" :: "r"(dsA + 10240 + (j << 3)),
                         "r"(packbf(l0, l1)), "r"(packbf(l2, l3)) : "memory");
            uint32_t g0 = packbf(bR[j].x, bR[j].y), g1 = packbf(bR[j].z, bR[j].w);
            float m0 = bR[j].x - __uint_as_float(g0 << 16);
            float m1 = bR[j].y - __uint_as_float(g0 & 0xffff0000u);
            float m2 = bR[j].z - __uint_as_float(g1 << 16);
            float m3 = bR[j].w - __uint_as_float(g1 & 0xffff0000u);
            asm volatile("st.shared.v2.b32 [%0], {%1,%2};" :: "r"(dsB + (j << 3)), "r"(g0), "r"(g1) : "memory");
            asm volatile("st.shared.v2.b32 [%0], {%1,%2};" :: "r"(dsB + 10240 + (j << 3)),
                         "r"(packbf(m0, m1)), "r"(packbf(m2, m3)) : "memory");
        } else {
            // A: fp16 hi + lo residual
            uint32_t h0 = packhf(aR[j].x, aR[j].y), h1 = packhf(aR[j].z, aR[j].w);
            float l0 = aR[j].x - h2f_lo(h0);
            float l1 = aR[j].y - h2f_hi(h0);
            float l2 = aR[j].z - h2f_lo(h1);
            float l3 = aR[j].w - h2f_hi(h1);
            asm volatile("st.shared.v2.b32 [%0], {%1,%2};" :: "r"(dsA + (j << 3)), "r"(h0), "r"(h1) : "memory");
            asm volatile("st.shared.v2.b32 [%0], {%1,%2};" :: "r"(dsA + 10240 + (j << 3)),
                         "r"(packhf(l0, l1)), "r"(packhf(l2, l3)) : "memory");
            // B: fp16 single
            asm volatile("st.shared.v2.b32 [%0], {%1,%2};" :: "r"(dsB + (j << 3)),
                         "r"(packhf(bR[j].x, bR[j].y)), "r"(packhf(bR[j].z, bR[j].w)) : "memory");
        }
    }
}

template<int BIASF, int GELUF, int RESF, int PREC>
__global__ __launch_bounds__(256, 1)
void gemm_mma(const float* __restrict__ A, const float* __restrict__ B,
              const float* __restrict__ bias, const float* __restrict__ res,
              float* __restrict__ C, int M, int N, int K)
{
    extern __shared__ char smem[];
    const uint32_t sb = smem_u32(smem);
    const int tid = threadIdx.x, wid = tid >> 5, lane = tid & 31;
    const int m0 = blockIdx.x << 7, n0 = blockIdx.y << 7;
    const int wm = (wid >> 2) << 6;
    const int wn = (wid & 3) << 5;

    const int lrow = tid >> 1;
    const int j0   = (tid & 1) << 2;
    const float* Ap = A + (size_t)(m0 + lrow) * K + (j0 << 2);
    const float* Bp = B + (size_t)(n0 + lrow) * K + (j0 << 2);
    const uint32_t stsOff = (uint32_t)(lrow * ROWB + (j0 << 3));

    float acc[4][4][4];
#pragma unroll
    for (int i = 0; i < 4; i++)
#pragma unroll
        for (int j = 0; j < 4; j++)
#pragma unroll
            for (int k = 0; k < 4; k++) acc[i][j][k] = 0.f;

    const int NC = K >> 5;
    float4 aR[4], bR[4];

    // prologue: chunk0 -> regs -> stage0; chunk1 -> regs
#pragma unroll
    for (int j = 0; j < 4; j++){
        aR[j] = *(const float4*)(Ap + (j << 2));
        bR[j] = *(const float4*)(Bp + (j << 2));
    }
    sts_chunk<PREC>(sb + stsOff, sb + stsOff + 20480, aR, bR);
    if (NC > 1){
#pragma unroll
        for (int j = 0; j < 4; j++){
            aR[j] = *(const float4*)(Ap + 32 + (j << 2));
            bR[j] = *(const float4*)(Bp + 32 + (j << 2));
        }
    }
    __syncthreads();

    const int g  = lane >> 3, lr = lane & 7;
    const int arow_off = ((g & 1) << 3) + lr;
    const int akb      = (g >> 1) << 4;
    const int brow_off = ((g >> 1) << 3) + lr;
    const int bkb      = (g & 1) << 4;

    int st_c = 0;   // stage of chunk c
    for (int c = 0; c < NC; c++){
        const uint32_t st = sb + st_c * STAGE_B;
        int st_n = (st_c == 2) ? 0 : st_c + 1;

        // store chunk c+1 (already in regs) into next stage
        if (c + 1 < NC){
            uint32_t d = sb + st_n * STAGE_B + stsOff;
            sts_chunk<PREC>(d, d + 20480, aR, bR);
        }
        // load chunk c+2 into regs
        if (c + 2 < NC){
#pragma unroll
            for (int j = 0; j < 4; j++){
                aR[j] = *(const float4*)(Ap + (size_t)(c + 2) * 32 + (j << 2));
                bR[j] = *(const float4*)(Bp + (size_t)(c + 2) * 32 + (j << 2));
            }
        }

        // compute on stage st
#pragma unroll
        for (int h = 0; h < 2; h++){
            uint32_t Ah[4][4], Al[4][4], Bh[4][2];
#pragma unroll
            for (int mt = 0; mt < 4; mt++){
                uint32_t ad = st + (uint32_t)((wm + (mt << 4) + arow_off) * ROWB + (h << 5) + akb);
                ldsm4(Ah[mt][0], Ah[mt][1], Ah[mt][2], Ah[mt][3], ad);
                ldsm4(Al[mt][0], Al[mt][1], Al[mt][2], Al[mt][3], ad + 10240);
            }
            if (PREC == 0){
                uint32_t Bl[4][2];
#pragma unroll
                for (int nt2 = 0; nt2 < 2; nt2++){
                    uint32_t bd = st + 20480 + (uint32_t)((wn + (nt2 << 4) + brow_off) * ROWB + (h << 5) + bkb);
                    uint32_t r0, r1, r2, r3;
                    ldsm4(r0, r1, r2, r3, bd);
                    Bh[2*nt2][0] = r0; Bh[2*nt2][1] = r1; Bh[2*nt2+1][0] = r2; Bh[2*nt2+1][1] = r3;
                    ldsm4(r0, r1, r2, r3, bd + 10240);
                    Bl[2*nt2][0] = r0; Bl[2*nt2][1] = r1; Bl[2*nt2+1][0] = r2; Bl[2*nt2+1][1] = r3;
                }
#pragma unroll
                for (int mt = 0; mt < 4; mt++)
#pragma unroll
                    for (int nt = 0; nt < 4; nt++){
                        mma16816(acc[mt][nt], Ah[mt], Bh[nt]);
                        mma16816(acc[mt][nt], Ah[mt], Bl[nt]);
                        mma16816(acc[mt][nt], Al[mt], Bh[nt]);
                    }
            } else {
#pragma unroll
                for (int nt2 = 0; nt2 < 2; nt2++){
                    uint32_t bd = st + 20480 + (uint32_t)((wn + (nt2 << 4) + brow_off) * ROWB + (h << 5) + bkb);
                    uint32_t r0, r1, r2, r3;
                    ldsm4(r0, r1, r2, r3, bd);
                    Bh[2*nt2][0] = r0; Bh[2*nt2][1] = r1; Bh[2*nt2+1][0] = r2; Bh[2*nt2+1][1] = r3;
                }
#pragma unroll
                for (int mt = 0; mt < 4; mt++)
#pragma unroll
                    for (int nt = 0; nt < 4; nt++){
                        mma16816h(acc[mt][nt], Ah[mt], Bh[nt]);
                        mma16816h(acc[mt][nt], Al[mt], Bh[nt]);
                    }
            }
        }
        __syncthreads();
        st_c = st_n;
    }

    const int qr = lane >> 2, qc = lane & 3;
#pragma unroll
    for (int mt = 0; mt < 4; mt++){
#pragma unroll
        for (int p = 0; p < 2; p++){
            int m = m0 + wm + (mt << 4) + qr + (p << 3);
            size_t rowbase = (size_t)m * N;
#pragma unroll
            for (int nt = 0; nt < 4; nt++){
                int n = n0 + wn + (nt << 3) + (qc << 1);
                float v0 = acc[mt][nt][2*p], v1 = acc[mt][nt][2*p + 1];
                if (BIASF){ v0 += bias[n]; v1 += bias[n + 1]; }
                if (GELUF){
                    v0 = 0.5f * v0 * (1.f + erff(v0 * 0.70710678118654752f));
                    v1 = 0.5f * v1 * (1.f + erff(v1 * 0.70710678118654752f));
                }
                if (RESF){
                    float2 rr = *(const float2*)&res[rowbase + n];
                    v0 += rr.x; v1 += rr.y;
                }
                *(float2*)&C[rowbase + n] = make_float2(v0, v1);
            }
        }
    }
}

// ================== tensor-core flash attention (unchanged from R6) ==================
#define AROWB 144
#define KOFF_LO  9216
#define VOFF_HI 18432
#define VOFF_LO 27648
#define ATT_STAGE 36864
#define ATT_SMEM (2*ATT_STAGE)

__global__ __launch_bounds__(256)
void attn_tc(){
    extern __shared__ char smc[];
    const uint32_t sb = smem_u32(smc);
    const int tid = threadIdx.x, wid = tid >> 5, lane = tid & 31;
    const int qb = gridDim.x - 1 - (int)blockIdx.x;
    const int hh = blockIdx.y;
    const int q0 = qb << 7;
    const int wq = q0 + (wid << 4);

    const float SCL = 0.125f * 1.4426950408889634f;
    uint32_t qh[4][4], ql[4][4];
    {
        int r0 = wq + (lane >> 2);
        int c0 = (lane & 3) << 1;
        const float* base = g_qkv + hh * DHH;
#pragma unroll
        for (int kt = 0; kt < 4; kt++){
#pragma unroll
            for (int rr = 0; rr < 2; rr++){
                const float* p = base + (size_t)(r0 + (rr << 3)) * QKV3 + (kt << 4) + c0;
                float2 f0 = *(const float2*)p;
                float2 f1 = *(const float2*)(p + 8);
                float x0 = f0.x*SCL, x1 = f0.y*SCL, x2 = f1.x*SCL, x3 = f1.y*SCL;
                uint32_t h0 = packbf(x0, x1), h1 = packbf(x2, x3);
                qh[kt][rr]     = h0;
                qh[kt][rr + 2] = h1;
                ql[kt][rr]     = packbf(x0 - __uint_as_float(h0 << 16),
                                        x1 - __uint_as_float(h0 & 0xffff0000u));
                ql[kt][rr + 2] = packbf(x2 - __uint_as_float(h1 << 16),
                                        x3 - __uint_as_float(h1 & 0xffff0000u));
            }
        }
    }

    float o[8][4];
#pragma unroll
    for (int i = 0; i < 8; i++){ o[i][0]=0.f; o[i][1]=0.f; o[i][2]=0.f; o[i][3]=0.f; }
    float mr0 = -INFINITY, mr1 = -INFINITY, lr0 = 0.f, lr1 = 0.f;

    const int jmax = (q0 >> 6) + 1;

    const int ldr = tid >> 2;
    const int ldc = (tid & 3) << 4;
    const float* kgp = g_qkv + (size_t)ldr * QKV3 + DD     + hh * DHH + ldc;
    const float* vgp = g_qkv + (size_t)ldr * QKV3 + 2 * DD + hh * DHH + ldc;

    float4 kf[4], vf[4];
#pragma unroll
    for (int t = 0; t < 4; t++){
        kf[t] = *(const float4*)(kgp + (t << 2));
        vf[t] = *(const float4*)(vgp + (t << 2));
    }

    const int g  = lane >> 3, lr8 = lane & 7;
    const int brow_off = ((g >> 1) << 3) + lr8;
    const int bkb      = (g & 1) << 4;
    const uint32_t sts_base = (uint32_t)(ldr * AROWB + (ldc << 1));

    for (int j = 0; j <= jmax; j++){
        const uint32_t st = sb + (j & 1) * ATT_STAGE;
        {
            *(uint4*)(smc + (st - sb) + sts_base) =
                make_uint4(packbf(kf[0].x,kf[0].y), packbf(kf[0].z,kf[0].w),
                           packbf(kf[1].x,kf[1].y), packbf(kf[1].z,kf[1].w));
            *(uint4*)(smc + (st - sb) + sts_base + 16) =
                make_uint4(packbf(kf[2].x,kf[2].y), packbf(kf[2].z,kf[2].w),
                           packbf(kf[3].x,kf[3].y), packbf(kf[3].z,kf[3].w));
            uint32_t kl0[4], l[4];
#pragma unroll
            for (int t = 0; t < 4; t++){
                uint32_t hh0 = packbf(kf[t].x, kf[t].y), hh1 = packbf(kf[t].z, kf[t].w);
                kl0[t] = packbf(kf[t].x - __uint_as_float(hh0 << 16),
                                kf[t].y - __uint_as_float(hh0 & 0xffff0000u));
                l[t]   = packbf(kf[t].z - __uint_as_float(hh1 << 16),
                                kf[t].w - __uint_as_float(hh1 & 0xffff0000u));
            }
            *(uint4*)(smc + (st - sb) + KOFF_LO + sts_base)      = make_uint4(kl0[0], l[0], kl0[1], l[1]);
            *(uint4*)(smc + (st - sb) + KOFF_LO + sts_base + 16) = make_uint4(kl0[2], l[2], kl0[3], l[3]);
            *(uint4*)(smc + (st - sb) + VOFF_HI + sts_base) =
                make_uint4(packbf(vf[0].x,vf[0].y), packbf(vf[0].z,vf[0].w),
                           packbf(vf[1].x,vf[1].y), packbf(vf[1].z,vf[1].w));
            *(uint4*)(smc + (st - sb) + VOFF_HI + sts_base + 16) =
                make_uint4(packbf(vf[2].x,vf[2].y), packbf(vf[2].z,vf[2].w),
                           packbf(vf[3].x,vf[3].y), packbf(vf[3].z,vf[3].w));
            uint32_t vl0[4], vl1[4];
#pragma unroll
            for (int t = 0; t < 4; t++){
                uint32_t hh0 = packbf(vf[t].x, vf[t].y), hh1 = packbf(vf[t].z, vf[t].w);
                vl0[t] = packbf(vf[t].x - __uint_as_float(hh0 << 16),
                                vf[t].y - __uint_as_float(hh0 & 0xffff0000u));
                vl1[t] = packbf(vf[t].z - __uint_as_float(hh1 << 16),
                                vf[t].w - __uint_as_float(hh1 & 0xffff0000u));
            }
            *(uint4*)(smc + (st - sb) + VOFF_LO + sts_base)      = make_uint4(vl0[0], vl1[0], vl0[1], vl1[1]);
            *(uint4*)(smc + (st - sb) + VOFF_LO + sts_base + 16) = make_uint4(vl0[2], vl1[2], vl0[3], vl1[3]);
        }
        __syncthreads();

        if (j < jmax){
            const float* kp2 = kgp + (size_t)((j + 1) << 6) * QKV3;
            const float* vp2 = vgp + (size_t)((j + 1) << 6) * QKV3;
#pragma unroll
            for (int t = 0; t < 4; t++){
                kf[t] = *(const float4*)(kp2 + (t << 2));
                vf[t] = *(const float4*)(vp2 + (t << 2));
            }
        }

        if ((j << 6) <= wq + 15){
            float s[8][4];
#pragma unroll
            for (int i = 0; i < 8; i++){ s[i][0]=0.f; s[i][1]=0.f; s[i][2]=0.f; s[i][3]=0.f; }
#pragma unroll
            for (int ks = 0; ks < 4; ks++){
                uint32_t kh[8][2], kl[8][2];
#pragma unroll
                for (int nt2 = 0; nt2 < 4; nt2++){
                    uint32_t ad = st + (uint32_t)(((nt2 << 4) + brow_off) * AROWB + (ks << 5) + bkb);
                    uint32_t r0, r1, r2, r3;
                    ldsm4(r0, r1, r2, r3, ad);
                    kh[2*nt2][0]=r0; kh[2*nt2][1]=r1; kh[2*nt2+1][0]=r2; kh[2*nt2+1][1]=r3;
                    ldsm4(r0, r1, r2, r3, ad + KOFF_LO);
                    kl[2*nt2][0]=r0; kl[2*nt2][1]=r1; kl[2*nt2+1][0]=r2; kl[2*nt2+1][1]=r3;
                }
#pragma unroll
                for (int nt = 0; nt < 8; nt++){
                    mma16816(s[nt], qh[ks], kh[nt]);
                    mma16816(s[nt], qh[ks], kl[nt]);
                    mma16816(s[nt], ql[ks], kh[nt]);
                }
            }
            if ((j << 6) + 63 > wq){
                int qr0 = wq + (lane >> 2);
#pragma unroll
                for (int nt = 0; nt < 8; nt++){
                    int kp = (j << 6) + (nt << 3) + ((lane & 3) << 1);
#pragma unroll
                    for (int e = 0; e < 4; e++){
                        int kpos = kp + (e & 1);
                        int qrow = qr0 + ((e >> 1) << 3);
                        if (kpos > qrow) s[nt][e] = -INFINITY;
                    }
                }
            }
            float mx0 = -INFINITY, mx1 = -INFINITY;
#pragma unroll
            for (int nt = 0; nt < 8; nt++){
                mx0 = fmaxf(mx0, fmaxf(s[nt][0], s[nt][1]));
                mx1 = fmaxf(mx1, fmaxf(s[nt][2], s[nt][3]));
            }
            mx0 = fmaxf(mx0, __shfl_xor_sync(0xffffffffu, mx0, 1));
            mx0 = fmaxf(mx0, __shfl_xor_sync(0xffffffffu, mx0, 2));
            mx1 = fmaxf(mx1, __shfl_xor_sync(0xffffffffu, mx1, 1));
            mx1 = fmaxf(mx1, __shfl_xor_sync(0xffffffffu, mx1, 2));
            float mn0 = fmaxf(mr0, mx0), mn1 = fmaxf(mr1, mx1);
            float a0 = ex2f(mr0 - mn0), a1 = ex2f(mr1 - mn1);
            mr0 = mn0; mr1 = mn1;
            lr0 *= a0; lr1 *= a1;
#pragma unroll
            for (int nt = 0; nt < 8; nt++){
                o[nt][0] *= a0; o[nt][1] *= a0; o[nt][2] *= a1; o[nt][3] *= a1;
            }
            float sum0 = 0.f, sum1 = 0.f;
#pragma unroll
            for (int nt = 0; nt < 8; nt++){
                s[nt][0] = ex2f(s[nt][0] - mn0);
                s[nt][1] = ex2f(s[nt][1] - mn0);
                s[nt][2] = ex2f(s[nt][2] - mn1);
                s[nt][3] = ex2f(s[nt][3] - mn1);
                sum0 += s[nt][0] + s[nt][1];
                sum1 += s[nt][2] + s[nt][3];
            }
            lr0 += sum0; lr1 += sum1;
#pragma unroll
            for (int kt = 0; kt < 4; kt++){
                uint32_t ph[4], pl[4];
                {
                    float p00 = s[2*kt][0],   p01 = s[2*kt][1];
                    float p10 = s[2*kt][2],   p11 = s[2*kt][3];
                    float p20 = s[2*kt+1][0], p21 = s[2*kt+1][1];
                    float p30 = s[2*kt+1][2], p31 = s[2*kt+1][3];
                    ph[0] = packbf(p00, p01); ph[1] = packbf(p10, p11);
                    ph[2] = packbf(p20, p21); ph[3] = packbf(p30, p31);
                    pl[0] = packbf(p00 - __uint_as_float(ph[0] << 16),
                                   p01 - __uint_as_float(ph[0] & 0xffff0000u));
                    pl[1] = packbf(p10 - __uint_as_float(ph[1] << 16),
                                   p11 - __uint_as_float(ph[1] & 0xffff0000u));
                    pl[2] = packbf(p20 - __uint_as_float(ph[2] << 16),
                                   p21 - __uint_as_float(ph[2] & 0xffff0000u));
                    pl[3] = packbf(p30 - __uint_as_float(ph[3] << 16),
                                   p31 - __uint_as_float(ph[3] & 0xffff0000u));
                }
#pragma unroll
                for (int nt2 = 0; nt2 < 4; nt2++){
                    uint32_t va = st + VOFF_HI +
                        (uint32_t)(((kt << 4) + (lane & 15)) * AROWB + (((nt2 << 4) + ((lane >> 4) << 3)) << 1));
                    uint32_t r0, r1, r2, r3;
                    ldsm4t(r0, r1, r2, r3, va);
                    uint32_t bh0[2] = {r0, r1}, bh1[2] = {r2, r3};
                    ldsm4t(r0, r1, r2, r3, va + (VOFF_LO - VOFF_HI));
                    uint32_t bl0[2] = {r0, r1}, bl1[2] = {r2, r3};
                    mma16816(o[2*nt2],   ph, bh0);
                    mma16816(o[2*nt2],   pl, bh0);
                    mma16816(o[2*nt2],   ph, bl0);
                    mma16816(o[2*nt2+1], ph, bh1);
                    mma16816(o[2*nt2+1], pl, bh1);
                    mma16816(o[2*nt2+1], ph, bl1);
                }
            }
        }
        __syncthreads();
    }

    lr0 += __shfl_xor_sync(0xffffffffu, lr0, 1);
    lr0 += __shfl_xor_sync(0xffffffffu, lr0, 2);
    lr1 += __shfl_xor_sync(0xffffffffu, lr1, 1);
    lr1 += __shfl_xor_sync(0xffffffffu, lr1, 2);
    float inv0 = 1.f / lr0, inv1 = 1.f / lr1;
    int qrow = wq + (lane >> 2);
    int cc = hh * DHH + ((lane & 3) << 1);
#pragma unroll
    for (int nt = 0; nt < 8; nt++){
        *(float2*)&g_ctx[(size_t)qrow * DD + cc + (nt << 3)] =
            make_float2(o[nt][0] * inv0, o[nt][1] * inv0);
        *(float2*)&g_ctx[(size_t)(qrow + 8) * DD + cc + (nt << 3)] =
            make_float2(o[nt][2] * inv1, o[nt][3] * inv1);
    }
}

// ---------------- loss ----------------
__global__ void row_lse_kernel(const float* __restrict__ logits, const int* __restrict__ tgt){
    int t = blockIdx.x;
    const float* row = logits + (size_t)t * VV;
    float mx = -INFINITY;
    for (int i = threadIdx.x; i < VV; i += blockDim.x) mx = fmaxf(mx, row[i]);
    mx = blockMax(mx);
    float s = 0.f;
    for (int i = threadIdx.x; i < VV; i += blockDim.x) s += expf(row[i] - mx);
    s = blockSum(s);
    if (threadIdx.x == 0){
        int tg = tgt[t];
        float lse = mx + logf(s);
        float nll = lse - row[tg];
        g_nll[t] = (tg != 0) ? nll : 0.f;
        g_val[t] = (tg != 0) ? 1.f : 0.f;
    }
}

__global__ void loss_reduce_kernel(float* __restrict__ out_loss){
    float a = 0.f, b = 0.f;
    for (int t = threadIdx.x; t < TT; t += blockDim.x){ a += g_nll[t]; b += g_val[t]; }
    a = blockSum(a);
    b = blockSum(b);
    if (threadIdx.x == 0) *out_loss = a / fmaxf(b, 1.f);
}

// ---------------- launch ----------------
extern "C" void kernel_launch(void* const* d_in, const int* in_sizes, int n_in,
                              void* d_out, int out_size){
    (void)in_sizes; (void)n_in;
    const int*   x     = (const int*)  d_in[0];
    const int*   tgt   = (const int*)  d_in[1];
    const float* tok   = (const float*)d_in[2];
    const float* pos   = (const float*)d_in[3];
    const float* Wqkv  = (const float*)d_in[4];
    const float* Wo    = (const float*)d_in[5];
    const float* ln1g  = (const float*)d_in[6];
    const float* ln1b  = (const float*)d_in[7];
    const float* ln2g  = (const float*)d_in[8];
    const float* ln2b  = (const float*)d_in[9];
    const float* W1    = (const float*)d_in[10];
    const float* b1    = (const float*)d_in[11];
    const float* W2    = (const float*)d_in[12];
    const float* b2    = (const float*)d_in[13];
    const float* lnfg  = (const float*)d_in[14];
    const float* lnfb  = (const float*)d_in[15];
    float* out = (float*)d_out;

    float *ph, *phn, *pqkv, *pctx, *pff;
    cudaGetSymbolAddress((void**)&ph,   g_h);
    cudaGetSymbolAddress((void**)&phn,  g_hn);
    cudaGetSymbolAddress((void**)&pqkv, g_qkv);
    cudaGetSymbolAddress((void**)&pctx, g_ctx);
    cudaGetSymbolAddress((void**)&pff,  g_ff);

    cudaFuncSetAttribute(gemm_mma<0,0,0,0>, cudaFuncAttributeMaxDynamicSharedMemorySize, G_SMEM);
    cudaFuncSetAttribute(gemm_mma<0,0,1,0>, cudaFuncAttributeMaxDynamicSharedMemorySize, G_SMEM);
    cudaFuncSetAttribute(gemm_mma<1,1,0,0>, cudaFuncAttributeMaxDynamicSharedMemorySize, G_SMEM);
    cudaFuncSetAttribute(gemm_mma<1,0,1,0>, cudaFuncAttributeMaxDynamicSharedMemorySize, G_SMEM);
    cudaFuncSetAttribute(gemm_mma<0,0,0,1>, cudaFuncAttributeMaxDynamicSharedMemorySize, G_SMEM);
    cudaFuncSetAttribute(attn_tc, cudaFuncAttributeMaxDynamicSharedMemorySize, ATT_SMEM);

    embed_kernel<<<TT, 256>>>(x, tok, pos);

    for (int l = 0; l < LL; l++){
        ln_kernel<<<TT, 256>>>(ph, phn, ln1g + l*DD, ln1b + l*DD);
        gemm_mma<0,0,0,0><<<dim3(TT/128, QKV3/128), 256, G_SMEM>>>(
            phn, Wqkv + (size_t)l*QKV3*DD, nullptr, nullptr, pqkv, TT, QKV3, DD);
        attn_tc<<<dim3(TT/128, HH), 256, ATT_SMEM>>>();
        gemm_mma<0,0,1,0><<<dim3(TT/128, DD/128), 256, G_SMEM>>>(
            pctx, Wo + (size_t)l*DD*DD, nullptr, ph, ph, TT, DD, DD);
        ln_kernel<<<TT, 256>>>(ph, phn, ln2g + l*DD, ln2b + l*DD);
        gemm_mma<1,1,0,0><<<dim3(TT/128, FFD/128), 256, G_SMEM>>>(
            phn, W1 + (size_t)l*FFD*DD, b1 + (size_t)l*FFD, nullptr, pff, TT, FFD, DD);
        gemm_mma<1,0,1,0><<<dim3(TT/128, DD/128), 256, G_SMEM>>>(
            pff, W2 + (size_t)l*DD*FFD, b2 + (size_t)l*DD, ph, ph, TT, DD, FFD);
    }

    ln_kernel<<<TT, 256>>>(ph, phn, lnfg, lnfb);
    gemm_mma<0,0,0,1><<<dim3(TT/128, VV/128), 256, G_SMEM>>>(
        phn, tok, nullptr, nullptr, out, TT, VV, DD);

    row_lse_kernel<<<TT, 256>>>(out, tgt);
    if (out_size > TT * VV)
        loss_reduce_kernel<<<1, 256>>>(out + (size_t)TT * VV);
}

// round 8
// speedup vs baseline: 2.8626x; 1.0926x over previous
#include <cuda_runtime.h>
#include <cuda_bf16.h>
#include <cuda_fp16.h>
#include <math.h>
#include <stdint.h>

// Problem constants
#define TT   2048
#define DD   768
#define HH   12
#define DHH  64
#define LL   6
#define FFD  3072
#define VV   32000
#define QKV3 (3*DD)

// ---------------- scratch ----------------
__device__ float g_h  [TT*DD];
__device__ float g_hn [TT*DD];
__device__ float g_qkv[TT*QKV3];
__device__ float g_ctx[TT*DD];
__device__ float g_ff [TT*FFD];
__device__ float g_nll[TT];
__device__ float g_val[TT];

// ---------------- helpers ----------------
__device__ __forceinline__ uint32_t smem_u32(const void* p){
    uint32_t a;
    asm("{ .reg .u64 t; cvta.to.shared.u64 t, %1; cvt.u32.u64 %0, t; }" : "=r"(a) : "l"(p));
    return a;
}
__device__ __forceinline__ uint32_t packbf(float x0, float x1){
    uint32_t r;
    asm("cvt.rn.bf16x2.f32 %0, %1, %2;" : "=r"(r) : "f"(x1), "f"(x0));
    return r;
}
__device__ __forceinline__ uint32_t packhf(float x0, float x1){
    uint32_t r;
    asm("cvt.rn.f16x2.f32 %0, %1, %2;" : "=r"(r) : "f"(x1), "f"(x0));
    return r;
}
__device__ __forceinline__ float h2f_lo(uint32_t p){
    float f; asm("{ .reg .b16 h, dummy; mov.b32 {h, dummy}, %1; cvt.f32.f16 %0, h; }" : "=f"(f) : "r"(p));
    return f;
}
__device__ __forceinline__ float h2f_hi(uint32_t p){
    float f; asm("{ .reg .b16 h, dummy; mov.b32 {dummy, h}, %1; cvt.f32.f16 %0, h; }" : "=f"(f) : "r"(p));
    return f;
}
__device__ __forceinline__ float ex2f(float x){
    float y; asm("ex2.approx.f32 %0, %1;" : "=f"(y) : "f"(x)); return y;
}
__device__ __forceinline__ void ldsm4(uint32_t &r0, uint32_t &r1, uint32_t &r2, uint32_t &r3,
                                      uint32_t addr){
    asm volatile("ldmatrix.sync.aligned.m8n8.x4.shared.b16 {%0,%1,%2,%3}, [%4];"
        : "=r"(r0), "=r"(r1), "=r"(r2), "=r"(r3) : "r"(addr));
}
__device__ __forceinline__ void ldsm4t(uint32_t &r0, uint32_t &r1, uint32_t &r2, uint32_t &r3,
                                       uint32_t addr){
    asm volatile("ldmatrix.sync.aligned.m8n8.x4.trans.shared.b16 {%0,%1,%2,%3}, [%4];"
        : "=r"(r0), "=r"(r1), "=r"(r2), "=r"(r3) : "r"(addr));
}
__device__ __forceinline__ void mma16816(float* d, const uint32_t* a, const uint32_t* b){
    asm volatile("mma.sync.aligned.m16n8k16.row.col.f32.bf16.bf16.f32 "
        "{%0,%1,%2,%3}, {%4,%5,%6,%7}, {%8,%9}, {%0,%1,%2,%3};"
        : "+f"(d[0]), "+f"(d[1]), "+f"(d[2]), "+f"(d[3])
        : "r"(a[0]), "r"(a[1]), "r"(a[2]), "r"(a[3]), "r"(b[0]), "r"(b[1]));
}
__device__ __forceinline__ void mma16816h(float* d, const uint32_t* a, const uint32_t* b){
    asm volatile("mma.sync.aligned.m16n8k16.row.col.f32.f16.f16.f32 "
        "{%0,%1,%2,%3}, {%4,%5,%6,%7}, {%8,%9}, {%0,%1,%2,%3};"
        : "+f"(d[0]), "+f"(d[1]), "+f"(d[2]), "+f"(d[3])
        : "r"(a[0]), "r"(a[1]), "r"(a[2]), "r"(a[3]), "r"(b[0]), "r"(b[1]));
}

// ---------------- reductions ----------------
__device__ __forceinline__ float warpSum(float v){
#pragma unroll
    for (int o = 16; o; o >>= 1) v += __shfl_xor_sync(0xffffffffu, v, o);
    return v;
}
__device__ __forceinline__ float warpMax(float v){
#pragma unroll
    for (int o = 16; o; o >>= 1) v = fmaxf(v, __shfl_xor_sync(0xffffffffu, v, o));
    return v;
}
__device__ float blockSum(float v){
    __shared__ float s[9];
    __syncthreads();
    int lane = threadIdx.x & 31, w = threadIdx.x >> 5;
    v = warpSum(v);
    if (lane == 0) s[w] = v;
    __syncthreads();
    if (w == 0){
        float x = (lane < (int)(blockDim.x >> 5)) ? s[lane] : 0.f;
        x = warpSum(x);
        if (lane == 0) s[8] = x;
    }
    __syncthreads();
    return s[8];
}
__device__ float blockMax(float v){
    __shared__ float s[9];
    __syncthreads();
    int lane = threadIdx.x & 31, w = threadIdx.x >> 5;
    v = warpMax(v);
    if (lane == 0) s[w] = v;
    __syncthreads();
    if (w == 0){
        float x = (lane < (int)(blockDim.x >> 5)) ? s[lane] : -INFINITY;
        x = warpMax(x);
        if (lane == 0) s[8] = x;
    }
    __syncthreads();
    return s[8];
}

// ---------------- embedding ----------------
__global__ void embed_kernel(const int* __restrict__ x,
                             const float* __restrict__ tok,
                             const float* __restrict__ pos){
    int t  = blockIdx.x;
    int id = x[t];
    const float* tr = tok + (size_t)id * DD;
    const float* pr = pos + (size_t)t  * DD;
    for (int d = threadIdx.x; d < DD; d += blockDim.x)
        g_h[t*DD + d] = tr[d] + pr[d];
}

// ---------------- layernorm ----------------
__global__ void ln_kernel(const float* __restrict__ in, float* __restrict__ out,
                          const float* __restrict__ g, const float* __restrict__ b){
    __shared__ float row[DD];
    int t = blockIdx.x;
    const float* r = in + (size_t)t * DD;
    float s = 0.f;
    for (int d = threadIdx.x; d < DD; d += blockDim.x){ float v = r[d]; row[d] = v; s += v; }
    s = blockSum(s);
    float mean = s * (1.f / DD);
    float q = 0.f;
    for (int d = threadIdx.x; d < DD; d += blockDim.x){ float v = row[d] - mean; q += v*v; }
    q = blockSum(q);
    float rstd = rsqrtf(q * (1.f / DD) + 1e-5f);
    for (int d = threadIdx.x; d < DD; d += blockDim.x)
        out[t*DD + d] = (row[d] - mean) * rstd * g[d] + b[d];
}

// ================== split tensor-core GEMM, 3-stage pipeline ==================
// C[M,N] = A[M,K] @ B[N,K]^T (+bias)(+gelu)(+res), fp32 in/out.
// 128x128 CTA tile, BK=32, 8 warps (2x4), warp tile 64x32.
// PREC=0: bf16 3-product (AhBh + AhBl + AlBh), residual ~2^-18.
// PREC=1: fp16 2-product (A split hi/lo, B single fp16), error ~2^-11 from B.
#define ROWB 80
#define STAGE_B 40960
#define G_SMEM (3*STAGE_B)

template<int PREC>
__device__ __forceinline__ void sts_chunk(uint32_t dsA, uint32_t dsB,
                                          const float4* aR, const float4* bR){
#pragma unroll
    for (int j = 0; j < 4; j++){
        if (PREC == 0){
            uint32_t h0 = packbf(aR[j].x, aR[j].y), h1 = packbf(aR[j].z, aR[j].w);
            float l0 = aR[j].x - __uint_as_float(h0 << 16);
            float l1 = aR[j].y - __uint_as_float(h0 & 0xffff0000u);
            float l2 = aR[j].z - __uint_as_float(h1 << 16);
            float l3 = aR[j].w - __uint_as_float(h1 & 0xffff0000u);
            asm volatile("st.shared.v2.b32 [%0], {%1,%2};" :: "r"(dsA + (j << 3)), "r"(h0), "r"(h1) : "memory");
            asm volatile("st.shared.v2.b32 [%0], {%1,%2};" :: "r"(dsA + 10240 + (j << 3)),
                         "r"(packbf(l0, l1)), "r"(packbf(l2, l3)) : "memory");
            uint32_t g0 = packbf(bR[j].x, bR[j].y), g1 = packbf(bR[j].z, bR[j].w);
            float m0 = bR[j].x - __uint_as_float(g0 << 16);
            float m1 = bR[j].y - __uint_as_float(g0 & 0xffff0000u);
            float m2 = bR[j].z - __uint_as_float(g1 << 16);
            float m3 = bR[j].w - __uint_as_float(g1 & 0xffff0000u);
            asm volatile("st.shared.v2.b32 [%0], {%1,%2};" :: "r"(dsB + (j << 3)), "r"(g0), "r"(g1) : "memory");
            asm volatile("st.shared.v2.b32 [%0], {%1,%2};" :: "r"(dsB + 10240 + (j << 3)),
                         "r"(packbf(m0, m1)), "r"(packbf(m2, m3)) : "memory");
        } else {
            uint32_t h0 = packhf(aR[j].x, aR[j].y), h1 = packhf(aR[j].z, aR[j].w);
            float l0 = aR[j].x - h2f_lo(h0);
            float l1 = aR[j].y - h2f_hi(h0);
            float l2 = aR[j].z - h2f_lo(h1);
            float l3 = aR[j].w - h2f_hi(h1);
            asm volatile("st.shared.v2.b32 [%0], {%1,%2};" :: "r"(dsA + (j << 3)), "r"(h0), "r"(h1) : "memory");
            asm volatile("st.shared.v2.b32 [%0], {%1,%2};" :: "r"(dsA + 10240 + (j << 3)),
                         "r"(packhf(l0, l1)), "r"(packhf(l2, l3)) : "memory");
            asm volatile("st.shared.v2.b32 [%0], {%1,%2};" :: "r"(dsB + (j << 3)),
                         "r"(packhf(bR[j].x, bR[j].y)), "r"(packhf(bR[j].z, bR[j].w)) : "memory");
        }
    }
}

template<int BIASF, int GELUF, int RESF, int PREC>
__global__ __launch_bounds__(256, 1)
void gemm_mma(const float* __restrict__ A, const float* __restrict__ B,
              const float* __restrict__ bias, const float* __restrict__ res,
              float* __restrict__ C, int M, int N, int K)
{
    extern __shared__ char smem[];
    const uint32_t sb = smem_u32(smem);
    const int tid = threadIdx.x, wid = tid >> 5, lane = tid & 31;
    const int m0 = blockIdx.x << 7, n0 = blockIdx.y << 7;
    const int wm = (wid >> 2) << 6;
    const int wn = (wid & 3) << 5;

    const int lrow = tid >> 1;
    const int j0   = (tid & 1) << 2;
    const float* Ap = A + (size_t)(m0 + lrow) * K + (j0 << 2);
    const float* Bp = B + (size_t)(n0 + lrow) * K + (j0 << 2);
    const uint32_t stsOff = (uint32_t)(lrow * ROWB + (j0 << 3));

    float acc[4][4][4];
#pragma unroll
    for (int i = 0; i < 4; i++)
#pragma unroll
        for (int j = 0; j < 4; j++)
#pragma unroll
            for (int k = 0; k < 4; k++) acc[i][j][k] = 0.f;

    const int NC = K >> 5;
    float4 aR[4], bR[4];

#pragma unroll
    for (int j = 0; j < 4; j++){
        aR[j] = *(const float4*)(Ap + (j << 2));
        bR[j] = *(const float4*)(Bp + (j << 2));
    }
    sts_chunk<PREC>(sb + stsOff, sb + stsOff + 20480, aR, bR);
    if (NC > 1){
#pragma unroll
        for (int j = 0; j < 4; j++){
            aR[j] = *(const float4*)(Ap + 32 + (j << 2));
            bR[j] = *(const float4*)(Bp + 32 + (j << 2));
        }
    }
    __syncthreads();

    const int g  = lane >> 3, lr = lane & 7;
    const int arow_off = ((g & 1) << 3) + lr;
    const int akb      = (g >> 1) << 4;
    const int brow_off = ((g >> 1) << 3) + lr;
    const int bkb      = (g & 1) << 4;

    int st_c = 0;
    for (int c = 0; c < NC; c++){
        const uint32_t st = sb + st_c * STAGE_B;
        int st_n = (st_c == 2) ? 0 : st_c + 1;

        if (c + 1 < NC){
            uint32_t d = sb + st_n * STAGE_B + stsOff;
            sts_chunk<PREC>(d, d + 20480, aR, bR);
        }
        if (c + 2 < NC){
#pragma unroll
            for (int j = 0; j < 4; j++){
                aR[j] = *(const float4*)(Ap + (size_t)(c + 2) * 32 + (j << 2));
                bR[j] = *(const float4*)(Bp + (size_t)(c + 2) * 32 + (j << 2));
            }
        }

#pragma unroll
        for (int h = 0; h < 2; h++){
            uint32_t Ah[4][4], Al[4][4], Bh[4][2];
#pragma unroll
            for (int mt = 0; mt < 4; mt++){
                uint32_t ad = st + (uint32_t)((wm + (mt << 4) + arow_off) * ROWB + (h << 5) + akb);
                ldsm4(Ah[mt][0], Ah[mt][1], Ah[mt][2], Ah[mt][3], ad);
                ldsm4(Al[mt][0], Al[mt][1], Al[mt][2], Al[mt][3], ad + 10240);
            }
            if (PREC == 0){
                uint32_t Bl[4][2];
#pragma unroll
                for (int nt2 = 0; nt2 < 2; nt2++){
                    uint32_t bd = st + 20480 + (uint32_t)((wn + (nt2 << 4) + brow_off) * ROWB + (h << 5) + bkb);
                    uint32_t r0, r1, r2, r3;
                    ldsm4(r0, r1, r2, r3, bd);
                    Bh[2*nt2][0] = r0; Bh[2*nt2][1] = r1; Bh[2*nt2+1][0] = r2; Bh[2*nt2+1][1] = r3;
                    ldsm4(r0, r1, r2, r3, bd + 10240);
                    Bl[2*nt2][0] = r0; Bl[2*nt2][1] = r1; Bl[2*nt2+1][0] = r2; Bl[2*nt2+1][1] = r3;
                }
#pragma unroll
                for (int mt = 0; mt < 4; mt++)
#pragma unroll
                    for (int nt = 0; nt < 4; nt++){
                        mma16816(acc[mt][nt], Ah[mt], Bh[nt]);
                        mma16816(acc[mt][nt], Ah[mt], Bl[nt]);
                        mma16816(acc[mt][nt], Al[mt], Bh[nt]);
                    }
            } else {
#pragma unroll
                for (int nt2 = 0; nt2 < 2; nt2++){
                    uint32_t bd = st + 20480 + (uint32_t)((wn + (nt2 << 4) + brow_off) * ROWB + (h << 5) + bkb);
                    uint32_t r0, r1, r2, r3;
                    ldsm4(r0, r1, r2, r3, bd);
                    Bh[2*nt2][0] = r0; Bh[2*nt2][1] = r1; Bh[2*nt2+1][0] = r2; Bh[2*nt2+1][1] = r3;
                }
#pragma unroll
                for (int mt = 0; mt < 4; mt++)
#pragma unroll
                    for (int nt = 0; nt < 4; nt++){
                        mma16816h(acc[mt][nt], Ah[mt], Bh[nt]);
                        mma16816h(acc[mt][nt], Al[mt], Bh[nt]);
                    }
            }
        }
        __syncthreads();
        st_c = st_n;
    }

    const int qr = lane >> 2, qc = lane & 3;
#pragma unroll
    for (int mt = 0; mt < 4; mt++){
#pragma unroll
        for (int p = 0; p < 2; p++){
            int m = m0 + wm + (mt << 4) + qr + (p << 3);
            size_t rowbase = (size_t)m * N;
#pragma unroll
            for (int nt = 0; nt < 4; nt++){
                int n = n0 + wn + (nt << 3) + (qc << 1);
                float v0 = acc[mt][nt][2*p], v1 = acc[mt][nt][2*p + 1];
                if (BIASF){ v0 += bias[n]; v1 += bias[n + 1]; }
                if (GELUF){
                    v0 = 0.5f * v0 * (1.f + erff(v0 * 0.70710678118654752f));
                    v1 = 0.5f * v1 * (1.f + erff(v1 * 0.70710678118654752f));
                }
                if (RESF){
                    float2 rr = *(const float2*)&res[rowbase + n];
                    v0 += rr.x; v1 += rr.y;
                }
                *(float2*)&C[rowbase + n] = make_float2(v0, v1);
            }
        }
    }
}

// ================== tensor-core flash attention ==================
#define AROWB 144
#define KOFF_LO  9216
#define VOFF_HI 18432
#define VOFF_LO 27648
#define ATT_STAGE 36864
#define ATT_SMEM (2*ATT_STAGE)

__global__ __launch_bounds__(256)
void attn_tc(){
    extern __shared__ char smc[];
    const uint32_t sb = smem_u32(smc);
    const int tid = threadIdx.x, wid = tid >> 5, lane = tid & 31;
    const int qb = gridDim.x - 1 - (int)blockIdx.x;
    const int hh = blockIdx.y;
    const int q0 = qb << 7;
    const int wq = q0 + (wid << 4);

    const float SCL = 0.125f * 1.4426950408889634f;
    uint32_t qh[4][4], ql[4][4];
    {
        int r0 = wq + (lane >> 2);
        int c0 = (lane & 3) << 1;
        const float* base = g_qkv + hh * DHH;
#pragma unroll
        for (int kt = 0; kt < 4; kt++){
#pragma unroll
            for (int rr = 0; rr < 2; rr++){
                const float* p = base + (size_t)(r0 + (rr << 3)) * QKV3 + (kt << 4) + c0;
                float2 f0 = *(const float2*)p;
                float2 f1 = *(const float2*)(p + 8);
                float x0 = f0.x*SCL, x1 = f0.y*SCL, x2 = f1.x*SCL, x3 = f1.y*SCL;
                uint32_t h0 = packbf(x0, x1), h1 = packbf(x2, x3);
                qh[kt][rr]     = h0;
                qh[kt][rr + 2] = h1;
                ql[kt][rr]     = packbf(x0 - __uint_as_float(h0 << 16),
                                        x1 - __uint_as_float(h0 & 0xffff0000u));
                ql[kt][rr + 2] = packbf(x2 - __uint_as_float(h1 << 16),
                                        x3 - __uint_as_float(h1 & 0xffff0000u));
            }
        }
    }

    float o[8][4];
#pragma unroll
    for (int i = 0; i < 8; i++){ o[i][0]=0.f; o[i][1]=0.f; o[i][2]=0.f; o[i][3]=0.f; }
    float mr0 = -INFINITY, mr1 = -INFINITY, lr0 = 0.f, lr1 = 0.f;

    const int jmax = (q0 >> 6) + 1;

    const int ldr = tid >> 2;
    const int ldc = (tid & 3) << 4;
    const float* kgp = g_qkv + (size_t)ldr * QKV3 + DD     + hh * DHH + ldc;
    const float* vgp = g_qkv + (size_t)ldr * QKV3 + 2 * DD + hh * DHH + ldc;

    float4 kf[4], vf[4];
#pragma unroll
    for (int t = 0; t < 4; t++){
        kf[t] = *(const float4*)(kgp + (t << 2));
        vf[t] = *(const float4*)(vgp + (t << 2));
    }

    const int g  = lane >> 3, lr8 = lane & 7;
    const int brow_off = ((g >> 1) << 3) + lr8;
    const int bkb      = (g & 1) << 4;
    const uint32_t sts_base = (uint32_t)(ldr * AROWB + (ldc << 1));

    for (int j = 0; j <= jmax; j++){
        const uint32_t st = sb + (j & 1) * ATT_STAGE;
        {
            *(uint4*)(smc + (st - sb) + sts_base) =
                make_uint4(packbf(kf[0].x,kf[0].y), packbf(kf[0].z,kf[0].w),
                           packbf(kf[1].x,kf[1].y), packbf(kf[1].z,kf[1].w));
            *(uint4*)(smc + (st - sb) + sts_base + 16) =
                make_uint4(packbf(kf[2].x,kf[2].y), packbf(kf[2].z,kf[2].w),
                           packbf(kf[3].x,kf[3].y), packbf(kf[3].z,kf[3].w));
            uint32_t kl0[4], l[4];
#pragma unroll
            for (int t = 0; t < 4; t++){
                uint32_t hh0 = packbf(kf[t].x, kf[t].y), hh1 = packbf(kf[t].z, kf[t].w);
                kl0[t] = packbf(kf[t].x - __uint_as_float(hh0 << 16),
                                kf[t].y - __uint_as_float(hh0 & 0xffff0000u));
                l[t]   = packbf(kf[t].z - __uint_as_float(hh1 << 16),
                                kf[t].w - __uint_as_float(hh1 & 0xffff0000u));
            }
            *(uint4*)(smc + (st - sb) + KOFF_LO + sts_base)      = make_uint4(kl0[0], l[0], kl0[1], l[1]);
            *(uint4*)(smc + (st - sb) + KOFF_LO + sts_base + 16) = make_uint4(kl0[2], l[2], kl0[3], l[3]);
            *(uint4*)(smc + (st - sb) + VOFF_HI + sts_base) =
                make_uint4(packbf(vf[0].x,vf[0].y), packbf(vf[0].z,vf[0].w),
                           packbf(vf[1].x,vf[1].y), packbf(vf[1].z,vf[1].w));
            *(uint4*)(smc + (st - sb) + VOFF_HI + sts_base + 16) =
                make_uint4(packbf(vf[2].x,vf[2].y), packbf(vf[2].z,vf[2].w),
                           packbf(vf[3].x,vf[3].y), packbf(vf[3].z,vf[3].w));
            uint32_t vl0[4], vl1[4];
#pragma unroll
            for (int t = 0; t < 4; t++){
                uint32_t hh0 = packbf(vf[t].x, vf[t].y), hh1 = packbf(vf[t].z, vf[t].w);
                vl0[t] = packbf(vf[t].x - __uint_as_float(hh0 << 16),
                                vf[t].y - __uint_as_float(hh0 & 0xffff0000u));
                vl1[t] = packbf(vf[t].z - __uint_as_float(hh1 << 16),
                                vf[t].w - __uint_as_float(hh1 & 0xffff0000u));
            }
            *(uint4*)(smc + (st - sb) + VOFF_LO + sts_base)      = make_uint4(vl0[0], vl1[0], vl0[1], vl1[1]);
            *(uint4*)(smc + (st - sb) + VOFF_LO + sts_base + 16) = make_uint4(vl0[2], vl1[2], vl0[3], vl1[3]);
        }
        __syncthreads();

        if (j < jmax){
            const float* kp2 = kgp + (size_t)((j + 1) << 6) * QKV3;
            const float* vp2 = vgp + (size_t)((j + 1) << 6) * QKV3;
#pragma unroll
            for (int t = 0; t < 4; t++){
                kf[t] = *(const float4*)(kp2 + (t << 2));
                vf[t] = *(const float4*)(vp2 + (t << 2));
            }
        }

        if ((j << 6) <= wq + 15){
            float s[8][4];
#pragma unroll
            for (int i = 0; i < 8; i++){ s[i][0]=0.f; s[i][1]=0.f; s[i][2]=0.f; s[i][3]=0.f; }
#pragma unroll
            for (int ks = 0; ks < 4; ks++){
                uint32_t kh[8][2], kl[8][2];
#pragma unroll
                for (int nt2 = 0; nt2 < 4; nt2++){
                    uint32_t ad = st + (uint32_t)(((nt2 << 4) + brow_off) * AROWB + (ks << 5) + bkb);
                    uint32_t r0, r1, r2, r3;
                    ldsm4(r0, r1, r2, r3, ad);
                    kh[2*nt2][0]=r0; kh[2*nt2][1]=r1; kh[2*nt2+1][0]=r2; kh[2*nt2+1][1]=r3;
                    ldsm4(r0, r1, r2, r3, ad + KOFF_LO);
                    kl[2*nt2][0]=r0; kl[2*nt2][1]=r1; kl[2*nt2+1][0]=r2; kl[2*nt2+1][1]=r3;
                }
#pragma unroll
                for (int nt = 0; nt < 8; nt++){
                    mma16816(s[nt], qh[ks], kh[nt]);
                    mma16816(s[nt], qh[ks], kl[nt]);
                    mma16816(s[nt], ql[ks], kh[nt]);
                }
            }
            if ((j << 6) + 63 > wq){
                int qr0 = wq + (lane >> 2);
#pragma unroll
                for (int nt = 0; nt < 8; nt++){
                    int kp = (j << 6) + (nt << 3) + ((lane & 3) << 1);
#pragma unroll
                    for (int e = 0; e < 4; e++){
                        int kpos = kp + (e & 1);
                        int qrow = qr0 + ((e >> 1) << 3);
                        if (kpos > qrow) s[nt][e] = -INFINITY;
                    }
                }
            }
            float mx0 = -INFINITY, mx1 = -INFINITY;
#pragma unroll
            for (int nt = 0; nt < 8; nt++){
                mx0 = fmaxf(mx0, fmaxf(s[nt][0], s[nt][1]));
                mx1 = fmaxf(mx1, fmaxf(s[nt][2], s[nt][3]));
            }
            mx0 = fmaxf(mx0, __shfl_xor_sync(0xffffffffu, mx0, 1));
            mx0 = fmaxf(mx0, __shfl_xor_sync(0xffffffffu, mx0, 2));
            mx1 = fmaxf(mx1, __shfl_xor_sync(0xffffffffu, mx1, 1));
            mx1 = fmaxf(mx1, __shfl_xor_sync(0xffffffffu, mx1, 2));
            float mn0 = fmaxf(mr0, mx0), mn1 = fmaxf(mr1, mx1);
            float a0 = ex2f(mr0 - mn0), a1 = ex2f(mr1 - mn1);
            mr0 = mn0; mr1 = mn1;
            lr0 *= a0; lr1 *= a1;
#pragma unroll
            for (int nt = 0; nt < 8; nt++){
                o[nt][0] *= a0; o[nt][1] *= a0; o[nt][2] *= a1; o[nt][3] *= a1;
            }
            float sum0 = 0.f, sum1 = 0.f;
#pragma unroll
            for (int nt = 0; nt < 8; nt++){
                s[nt][0] = ex2f(s[nt][0] - mn0);
                s[nt][1] = ex2f(s[nt][1] - mn0);
                s[nt][2] = ex2f(s[nt][2] - mn1);
                s[nt][3] = ex2f(s[nt][3] - mn1);
                sum0 += s[nt][0] + s[nt][1];
                sum1 += s[nt][2] + s[nt][3];
            }
            lr0 += sum0; lr1 += sum1;
#pragma unroll
            for (int kt = 0; kt < 4; kt++){
                uint32_t ph[4], pl[4];
                {
                    float p00 = s[2*kt][0],   p01 = s[2*kt][1];
                    float p10 = s[2*kt][2],   p11 = s[2*kt][3];
                    float p20 = s[2*kt+1][0], p21 = s[2*kt+1][1];
                    float p30 = s[2*kt+1][2], p31 = s[2*kt+1][3];
                    ph[0] = packbf(p00, p01); ph[1] = packbf(p10, p11);
                    ph[2] = packbf(p20, p21); ph[3] = packbf(p30, p31);
                    pl[0] = packbf(p00 - __uint_as_float(ph[0] << 16),
                                   p01 - __uint_as_float(ph[0] & 0xffff0000u));
                    pl[1] = packbf(p10 - __uint_as_float(ph[1] << 16),
                                   p11 - __uint_as_float(ph[1] & 0xffff0000u));
                    pl[2] = packbf(p20 - __uint_as_float(ph[2] << 16),
                                   p21 - __uint_as_float(ph[2] & 0xffff0000u));
                    pl[3] = packbf(p30 - __uint_as_float(ph[3] << 16),
                                   p31 - __uint_as_float(ph[3] & 0xffff0000u));
                }
#pragma unroll
                for (int nt2 = 0; nt2 < 4; nt2++){
                    uint32_t va = st + VOFF_HI +
                        (uint32_t)(((kt << 4) + (lane & 15)) * AROWB + (((nt2 << 4) + ((lane >> 4) << 3)) << 1));
                    uint32_t r0, r1, r2, r3;
                    ldsm4t(r0, r1, r2, r3, va);
                    uint32_t bh0[2] = {r0, r1}, bh1[2] = {r2, r3};
                    ldsm4t(r0, r1, r2, r3, va + (VOFF_LO - VOFF_HI));
                    uint32_t bl0[2] = {r0, r1}, bl1[2] = {r2, r3};
                    mma16816(o[2*nt2],   ph, bh0);
                    mma16816(o[2*nt2],   pl, bh0);
                    mma16816(o[2*nt2],   ph, bl0);
                    mma16816(o[2*nt2+1], ph, bh1);
                    mma16816(o[2*nt2+1], pl, bh1);
                    mma16816(o[2*nt2+1], ph, bl1);
                }
            }
        }
        __syncthreads();
    }

    lr0 += __shfl_xor_sync(0xffffffffu, lr0, 1);
    lr0 += __shfl_xor_sync(0xffffffffu, lr0, 2);
    lr1 += __shfl_xor_sync(0xffffffffu, lr1, 1);
    lr1 += __shfl_xor_sync(0xffffffffu, lr1, 2);
    float inv0 = 1.f / lr0, inv1 = 1.f / lr1;
    int qrow = wq + (lane >> 2);
    int cc = hh * DHH + ((lane & 3) << 1);
#pragma unroll
    for (int nt = 0; nt < 8; nt++){
        *(float2*)&g_ctx[(size_t)qrow * DD + cc + (nt << 3)] =
            make_float2(o[nt][0] * inv0, o[nt][1] * inv0);
        *(float2*)&g_ctx[(size_t)(qrow + 8) * DD + cc + (nt << 3)] =
            make_float2(o[nt][2] * inv1, o[nt][3] * inv1);
    }
}

// ---------------- loss ----------------
__global__ void row_lse_kernel(const float* __restrict__ logits, const int* __restrict__ tgt){
    int t = blockIdx.x;
    const float* row = logits + (size_t)t * VV;
    float mx = -INFINITY;
    for (int i = threadIdx.x; i < VV; i += blockDim.x) mx = fmaxf(mx, row[i]);
    mx = blockMax(mx);
    float s = 0.f;
    for (int i = threadIdx.x; i < VV; i += blockDim.x) s += expf(row[i] - mx);
    s = blockSum(s);
    if (threadIdx.x == 0){
        int tg = tgt[t];
        float lse = mx + logf(s);
        float nll = lse - row[tg];
        g_nll[t] = (tg != 0) ? nll : 0.f;
        g_val[t] = (tg != 0) ? 1.f : 0.f;
    }
}

__global__ void loss_reduce_kernel(float* __restrict__ out_loss){
    float a = 0.f, b = 0.f;
    for (int t = threadIdx.x; t < TT; t += blockDim.x){ a += g_nll[t]; b += g_val[t]; }
    a = blockSum(a);
    b = blockSum(b);
    if (threadIdx.x == 0) *out_loss = a / fmaxf(b, 1.f);
}

// ---------------- launch ----------------
extern "C" void kernel_launch(void* const* d_in, const int* in_sizes, int n_in,
                              void* d_out, int out_size){
    (void)in_sizes; (void)n_in;
    const int*   x     = (const int*)  d_in[0];
    const int*   tgt   = (const int*)  d_in[1];
    const float* tok   = (const float*)d_in[2];
    const float* pos   = (const float*)d_in[3];
    const float* Wqkv  = (const float*)d_in[4];
    const float* Wo    = (const float*)d_in[5];
    const float* ln1g  = (const float*)d_in[6];
    const float* ln1b  = (const float*)d_in[7];
    const float* ln2g  = (const float*)d_in[8];
    const float* ln2b  = (const float*)d_in[9];
    const float* W1    = (const float*)d_in[10];
    const float* b1    = (const float*)d_in[11];
    const float* W2    = (const float*)d_in[12];
    const float* b2    = (const float*)d_in[13];
    const float* lnfg  = (const float*)d_in[14];
    const float* lnfb  = (const float*)d_in[15];
    float* out = (float*)d_out;

    float *ph, *phn, *pqkv, *pctx, *pff;
    cudaGetSymbolAddress((void**)&ph,   g_h);
    cudaGetSymbolAddress((void**)&phn,  g_hn);
    cudaGetSymbolAddress((void**)&pqkv, g_qkv);
    cudaGetSymbolAddress((void**)&pctx, g_ctx);
    cudaGetSymbolAddress((void**)&pff,  g_ff);

    cudaFuncSetAttribute(gemm_mma<0,0,0,1>, cudaFuncAttributeMaxDynamicSharedMemorySize, G_SMEM);
    cudaFuncSetAttribute(gemm_mma<0,0,1,1>, cudaFuncAttributeMaxDynamicSharedMemorySize, G_SMEM);
    cudaFuncSetAttribute(gemm_mma<1,1,0,1>, cudaFuncAttributeMaxDynamicSharedMemorySize, G_SMEM);
    cudaFuncSetAttribute(gemm_mma<1,0,1,1>, cudaFuncAttributeMaxDynamicSharedMemorySize, G_SMEM);
    cudaFuncSetAttribute(attn_tc, cudaFuncAttributeMaxDynamicSharedMemorySize, ATT_SMEM);

    embed_kernel<<<TT, 256>>>(x, tok, pos);

    for (int l = 0; l < LL; l++){
        ln_kernel<<<TT, 256>>>(ph, phn, ln1g + l*DD, ln1b + l*DD);
        gemm_mma<0,0,0,1><<<dim3(TT/128, QKV3/128), 256, G_SMEM>>>(
            phn, Wqkv + (size_t)l*QKV3*DD, nullptr, nullptr, pqkv, TT, QKV3, DD);
        attn_tc<<<dim3(TT/128, HH), 256, ATT_SMEM>>>();
        gemm_mma<0,0,1,1><<<dim3(TT/128, DD/128), 256, G_SMEM>>>(
            pctx, Wo + (size_t)l*DD*DD, nullptr, ph, ph, TT, DD, DD);
        ln_kernel<<<TT, 256>>>(ph, phn, ln2g + l*DD, ln2b + l*DD);
        gemm_mma<1,1,0,1><<<dim3(TT/128, FFD/128), 256, G_SMEM>>>(
            phn, W1 + (size_t)l*FFD*DD, b1 + (size_t)l*FFD, nullptr, pff, TT, FFD, DD);
        gemm_mma<1,0,1,1><<<dim3(TT/128, DD/128), 256, G_SMEM>>>(
            pff, W2 + (size_t)l*DD*FFD, b2 + (size_t)l*DD, ph, ph, TT, DD, FFD);
    }

    ln_kernel<<<TT, 256>>>(ph, phn, lnfg, lnfb);
    gemm_mma<0,0,0,1><<<dim3(TT/128, VV/128), 256, G_SMEM>>>(
        phn, tok, nullptr, nullptr, out, TT, VV, DD);

    row_lse_kernel<<<TT, 256>>>(out, tgt);
    if (out_size > TT * VV)
        loss_reduce_kernel<<<1, 256>>>(out + (size_t)TT * VV);
}